// round 2
// baseline (speedup 1.0000x reference)
#include <cuda_runtime.h>
#include <math.h>

// Problem constants
#define BATCH 128
#define TT    512            // timesteps
#define BT    65536          // BATCH * TT
#define DIN   409            // 300 + 74 + 35
#define DPAD  416            // padded to multiple of 16
#define HD    1024           // hidden dim
#define G4    4096           // 4 * HD (gates)
#define CD    512            // fc1 output
#define OD    7              // classes

// -------------------- scratch (static __device__, no allocs) --------------------
__device__ float g_xcat[(size_t)BT * DPAD];     // packed+padded concat input
__device__ float g_Wx[(size_t)DPAD * G4];       // W_ih^T, gate-interleaved [k][4j+g]
__device__ float g_bias[G4];                    // b_ih + b_hh, gate-interleaved
__device__ float g_Wh[(size_t)HD * G4];         // W_hh^T, gate-interleaved
__device__ float g_xg[(size_t)BT * G4];         // x_gates  (1 GB)
__device__ float g_h[2][BATCH * HD];            // double-buffered h
__device__ float g_c[BATCH * HD];               // cell state
__device__ float g_hall[(size_t)BT * HD];       // all h outputs (256 MB)
__device__ float g_fc1T[(size_t)HD * CD];       // fc1_w^T
__device__ float g_hidden[(size_t)BT * CD];     // relu(fc1) activations (134 MB)

__device__ __forceinline__ float sigmoidf(float x) {
    return 1.0f / (1.0f + expf(-x));
}

// -------------------- input packing: concat 3 modalities, zero-pad to 416 ----
__global__ void k_pack(const float* __restrict__ mt,
                       const float* __restrict__ ma,
                       const float* __restrict__ mv) {
    size_t idx = (size_t)blockIdx.x * blockDim.x + threadIdx.x;
    if (idx >= (size_t)BT * DPAD) return;
    size_t row = idx / DPAD;
    int    col = (int)(idx % DPAD);
    float v = 0.0f;
    if (col < 300)      v = mt[row * 300 + col];
    else if (col < 374) v = ma[row * 74 + (col - 300)];
    else if (col < 409) v = mv[row * 35 + (col - 374)];
    g_xcat[idx] = v;
}

// -------------------- weight layout transforms (gate-interleaved) ------------
__global__ void k_prep_wx(const float* __restrict__ W_ih) {
    int idx = blockIdx.x * blockDim.x + threadIdx.x;       // over DPAD*G4
    if (idx >= DPAD * G4) return;
    int k = idx / G4, n = idx % G4;
    int j = n >> 2, g = n & 3;
    g_Wx[idx] = (k < DIN) ? W_ih[(size_t)(g * HD + j) * DIN + k] : 0.0f;
}
__global__ void k_prep_wh(const float* __restrict__ W_hh) {
    int idx = blockIdx.x * blockDim.x + threadIdx.x;       // over HD*G4
    if (idx >= HD * G4) return;
    int k = idx / G4, n = idx % G4;
    int j = n >> 2, g = n & 3;
    g_Wh[idx] = W_hh[(size_t)(g * HD + j) * HD + k];
}
__global__ void k_prep_bias(const float* __restrict__ b_ih,
                            const float* __restrict__ b_hh) {
    int n = blockIdx.x * blockDim.x + threadIdx.x;
    if (n >= G4) return;
    int j = n >> 2, g = n & 3;
    g_bias[n] = b_ih[g * HD + j] + b_hh[g * HD + j];
}
__global__ void k_prep_fc1(const float* __restrict__ fc1_w) {
    int idx = blockIdx.x * blockDim.x + threadIdx.x;       // over HD*CD
    if (idx >= HD * CD) return;
    int k = idx / CD, n = idx % CD;
    g_fc1T[idx] = fc1_w[(size_t)n * HD + k];
}
__global__ void k_zero_state() {
    int idx = blockIdx.x * blockDim.x + threadIdx.x;
    if (idx >= BATCH * HD) return;
    g_h[0][idx] = 0.0f;
    g_c[idx] = 0.0f;
}

// -------------------- generic fp32 SGEMM: C = A[MxK] * B[KxN] + bias ---------
// BM=BN=128, BK=16, TM=TN=8, 256 threads. M,N multiples of 128; K multiple of 16.
template <int RELU>
__global__ __launch_bounds__(256) void sgemm128(
    const float* __restrict__ A, const float* __restrict__ B,
    float* __restrict__ C, int M, int N, int K,
    const float* __restrict__ bias) {
    __shared__ float As[16][128];   // transposed: As[k][m]
    __shared__ float Bs[16][128];
    const int tid = threadIdx.x;
    const int bm = blockIdx.y, bn = blockIdx.x;

    const float* Ab = A + (size_t)bm * 128 * K;
    const float* Bb = B + (size_t)bn * 128;

    const int arow = tid >> 2;            // 0..63  (also +64)
    const int acol = (tid & 3) * 4;       // 0,4,8,12
    const int brow = tid >> 5;            // 0..7   (also +8)
    const int bcol = (tid & 31) * 4;

    const int tx = tid & 15, ty = tid >> 4;

    float acc[8][8];
#pragma unroll
    for (int i = 0; i < 8; i++)
#pragma unroll
        for (int j = 0; j < 8; j++) acc[i][j] = 0.0f;

    for (int k0 = 0; k0 < K; k0 += 16) {
        float4 a0 = *(const float4*)(Ab + (size_t)arow * K + k0 + acol);
        float4 a1 = *(const float4*)(Ab + (size_t)(arow + 64) * K + k0 + acol);
        float4 b0 = *(const float4*)(Bb + (size_t)(k0 + brow) * N + bcol);
        float4 b1 = *(const float4*)(Bb + (size_t)(k0 + brow + 8) * N + bcol);

        As[acol + 0][arow] = a0.x;  As[acol + 1][arow] = a0.y;
        As[acol + 2][arow] = a0.z;  As[acol + 3][arow] = a0.w;
        As[acol + 0][arow + 64] = a1.x;  As[acol + 1][arow + 64] = a1.y;
        As[acol + 2][arow + 64] = a1.z;  As[acol + 3][arow + 64] = a1.w;
        *(float4*)&Bs[brow][bcol] = b0;
        *(float4*)&Bs[brow + 8][bcol] = b1;
        __syncthreads();

#pragma unroll
        for (int k = 0; k < 16; k++) {
            float4 ra0 = *(const float4*)&As[k][ty * 8];
            float4 ra1 = *(const float4*)&As[k][ty * 8 + 4];
            float4 rb0 = *(const float4*)&Bs[k][tx * 8];
            float4 rb1 = *(const float4*)&Bs[k][tx * 8 + 4];
            float ra[8] = {ra0.x, ra0.y, ra0.z, ra0.w, ra1.x, ra1.y, ra1.z, ra1.w};
            float rb[8] = {rb0.x, rb0.y, rb0.z, rb0.w, rb1.x, rb1.y, rb1.z, rb1.w};
#pragma unroll
            for (int i = 0; i < 8; i++)
#pragma unroll
                for (int j = 0; j < 8; j++) acc[i][j] = fmaf(ra[i], rb[j], acc[i][j]);
        }
        __syncthreads();
    }

    // epilogue: + bias (, ReLU), write
    float bv[8];
    {
        float4 q0 = *(const float4*)(bias + bn * 128 + tx * 8);
        float4 q1 = *(const float4*)(bias + bn * 128 + tx * 8 + 4);
        bv[0] = q0.x; bv[1] = q0.y; bv[2] = q0.z; bv[3] = q0.w;
        bv[4] = q1.x; bv[5] = q1.y; bv[6] = q1.z; bv[7] = q1.w;
    }
#pragma unroll
    for (int i = 0; i < 8; i++) {
        size_t m = (size_t)bm * 128 + ty * 8 + i;
        float* Crow = C + m * N + (size_t)bn * 128 + tx * 8;
        float v[8];
#pragma unroll
        for (int j = 0; j < 8; j++) {
            float t = acc[i][j] + bv[j];
            if (RELU) t = fmaxf(t, 0.0f);
            v[j] = t;
        }
        *(float4*)(Crow)     = make_float4(v[0], v[1], v[2], v[3]);
        *(float4*)(Crow + 4) = make_float4(v[4], v[5], v[6], v[7]);
    }
}

// -------------------- fused LSTM step: gates GEMM + pointwise ----------------
// grid 128 blocks: each computes gate columns [32*bx, 32*bx+32) = 8 hidden units
// for all 128 batch rows, then applies the LSTM cell update in-epilogue.
__global__ __launch_bounds__(256) void lstm_step(int t) {
    __shared__ float Hs[32][128];   // transposed: Hs[k][m]
    __shared__ float Ws[32][32];
    const int tid = threadIdx.x;
    const int n0 = blockIdx.x * 32;

    const float* __restrict__ hprev = g_h[t & 1];
    float* __restrict__ hnext = g_h[(t + 1) & 1];

    const int arow = tid >> 3;          // 0..31 (rows +0,+32,+64,+96)
    const int acol = (tid & 7) * 4;     // 0..28
    const int brow = tid >> 3;          // 0..31
    const int bcol = (tid & 7) * 4;

    const int tx = tid & 7;             // unit within tile (0..7)
    const int ty = tid >> 3;            // row-group (0..31)

    float acc[4][4];
#pragma unroll
    for (int i = 0; i < 4; i++)
#pragma unroll
        for (int j = 0; j < 4; j++) acc[i][j] = 0.0f;

    for (int k0 = 0; k0 < HD; k0 += 32) {
        float4 a0 = *(const float4*)(hprev + (size_t)(arow +  0) * HD + k0 + acol);
        float4 a1 = *(const float4*)(hprev + (size_t)(arow + 32) * HD + k0 + acol);
        float4 a2 = *(const float4*)(hprev + (size_t)(arow + 64) * HD + k0 + acol);
        float4 a3 = *(const float4*)(hprev + (size_t)(arow + 96) * HD + k0 + acol);
        float4 wb = *(const float4*)(g_Wh + (size_t)(k0 + brow) * G4 + n0 + bcol);

        Hs[acol + 0][arow]      = a0.x; Hs[acol + 1][arow]      = a0.y;
        Hs[acol + 2][arow]      = a0.z; Hs[acol + 3][arow]      = a0.w;
        Hs[acol + 0][arow + 32] = a1.x; Hs[acol + 1][arow + 32] = a1.y;
        Hs[acol + 2][arow + 32] = a1.z; Hs[acol + 3][arow + 32] = a1.w;
        Hs[acol + 0][arow + 64] = a2.x; Hs[acol + 1][arow + 64] = a2.y;
        Hs[acol + 2][arow + 64] = a2.z; Hs[acol + 3][arow + 64] = a2.w;
        Hs[acol + 0][arow + 96] = a3.x; Hs[acol + 1][arow + 96] = a3.y;
        Hs[acol + 2][arow + 96] = a3.z; Hs[acol + 3][arow + 96] = a3.w;
        *(float4*)&Ws[brow][bcol] = wb;
        __syncthreads();

#pragma unroll
        for (int k = 0; k < 32; k++) {
            float4 ra = *(const float4*)&Hs[k][ty * 4];
            float4 rb = *(const float4*)&Ws[k][tx * 4];
            float a[4] = {ra.x, ra.y, ra.z, ra.w};
            float b[4] = {rb.x, rb.y, rb.z, rb.w};
#pragma unroll
            for (int i = 0; i < 4; i++)
#pragma unroll
                for (int j = 0; j < 4; j++) acc[i][j] = fmaf(a[i], b[j], acc[i][j]);
        }
        __syncthreads();
    }

    // epilogue: LSTM cell update for unit u, rows ty*4..ty*4+3
    const int u = (n0 >> 2) + tx;       // global hidden unit
#pragma unroll
    for (int r = 0; r < 4; r++) {
        int b = ty * 4 + r;
        size_t xg = ((size_t)b * TT + t) * G4 + n0 + tx * 4;
        float gi = acc[r][0] + g_xg[xg + 0];
        float gf = acc[r][1] + g_xg[xg + 1];
        float gg = acc[r][2] + g_xg[xg + 2];
        float go = acc[r][3] + g_xg[xg + 3];
        float iv = sigmoidf(gi);
        float fv = sigmoidf(gf);
        float gv = tanhf(gg);
        float ov = sigmoidf(go);
        float cp = g_c[b * HD + u];
        float cn = fmaf(fv, cp, iv * gv);
        float hn = ov * tanhf(cn);
        g_c[b * HD + u] = cn;
        hnext[b * HD + u] = hn;
        g_hall[((size_t)b * TT + t) * HD + u] = hn;
    }
}

// -------------------- head: fc2 (N=7) + log_softmax, warp per row ------------
__global__ __launch_bounds__(256) void head_kernel(const float* __restrict__ fc2_w,
                                                   const float* __restrict__ fc2_b,
                                                   float* __restrict__ out) {
    __shared__ float ws[OD][CD];
    const int tid = threadIdx.x;
    for (int i = tid; i < OD * CD; i += 256) ws[i / CD][i % CD] = fc2_w[i];
    __syncthreads();

    const int warp = tid >> 5, lane = tid & 31;
    size_t row = (size_t)blockIdx.x * 8 + warp;
    const float* h = g_hidden + row * CD;

    float p[OD];
#pragma unroll
    for (int o = 0; o < OD; o++) p[o] = 0.0f;

    for (int k = lane; k < CD; k += 32) {
        float hv = h[k];
#pragma unroll
        for (int o = 0; o < OD; o++) p[o] = fmaf(hv, ws[o][k], p[o]);
    }
#pragma unroll
    for (int o = 0; o < OD; o++)
#pragma unroll
        for (int s = 16; s > 0; s >>= 1)
            p[o] += __shfl_xor_sync(0xFFFFFFFFu, p[o], s);

    float z[OD], m = -1e30f;
#pragma unroll
    for (int o = 0; o < OD; o++) { z[o] = p[o] + fc2_b[o]; m = fmaxf(m, z[o]); }
    float s = 0.0f;
#pragma unroll
    for (int o = 0; o < OD; o++) s += expf(z[o] - m);
    float lse = m + logf(s);
    if (lane < OD) out[row * OD + lane] = z[lane] - lse;
}

// -------------------- launch ------------------------------------------------
extern "C" void kernel_launch(void* const* d_in, const int* in_sizes, int n_in,
                              void* d_out, int out_size) {
    const float* m_text  = (const float*)d_in[0];
    const float* m_audio = (const float*)d_in[1];
    const float* m_video = (const float*)d_in[2];
    // d_in[3] dummy_lengths, d_in[4] dummy_labels: unused
    const float* W_ih  = (const float*)d_in[5];
    const float* W_hh  = (const float*)d_in[6];
    const float* b_ih  = (const float*)d_in[7];
    const float* b_hh  = (const float*)d_in[8];
    const float* fc1_w = (const float*)d_in[9];
    const float* fc1_b = (const float*)d_in[10];
    const float* fc2_w = (const float*)d_in[11];
    const float* fc2_b = (const float*)d_in[12];
    float* out = (float*)d_out;

    float *p_xcat, *p_Wx, *p_bias, *p_xg, *p_hall, *p_fc1T, *p_hidden;
    cudaGetSymbolAddress((void**)&p_xcat,   g_xcat);
    cudaGetSymbolAddress((void**)&p_Wx,     g_Wx);
    cudaGetSymbolAddress((void**)&p_bias,   g_bias);
    cudaGetSymbolAddress((void**)&p_xg,     g_xg);
    cudaGetSymbolAddress((void**)&p_hall,   g_hall);
    cudaGetSymbolAddress((void**)&p_fc1T,   g_fc1T);
    cudaGetSymbolAddress((void**)&p_hidden, g_hidden);

    // 1. pack + weight transforms
    {
        size_t n = (size_t)BT * DPAD;
        k_pack<<<(unsigned)((n + 255) / 256), 256>>>(m_text, m_audio, m_video);
    }
    k_prep_wx<<<(DPAD * G4 + 255) / 256, 256>>>(W_ih);
    k_prep_wh<<<(HD * G4 + 255) / 256, 256>>>(W_hh);
    k_prep_bias<<<(G4 + 255) / 256, 256>>>(b_ih, b_hh);
    k_prep_fc1<<<(HD * CD + 255) / 256, 256>>>(fc1_w);

    // 2. x_gates = xcat @ Wx + (b_ih + b_hh)   [65536 x 4096]
    {
        dim3 grid(G4 / 128, BT / 128);
        sgemm128<0><<<grid, 256>>>(p_xcat, p_Wx, p_xg, BT, G4, DPAD, p_bias);
    }

    // 3. recurrence: 512 fused step kernels
    k_zero_state<<<(BATCH * HD + 255) / 256, 256>>>();
    for (int t = 0; t < TT; t++) {
        lstm_step<<<G4 / 32, 256>>>(t);
    }

    // 4. head: fc1 + ReLU, then fc2 + log_softmax
    {
        dim3 grid(CD / 128, BT / 128);
        sgemm128<1><<<grid, 256>>>(p_hall, p_fc1T, p_hidden, BT, CD, HD, fc1_b);
    }
    head_kernel<<<BT / 8, 256>>>(fc2_w, fc2_b, out);
}

// round 3
// speedup vs baseline: 2.0025x; 2.0025x over previous
#include <cuda_runtime.h>
#include <math.h>

// Problem constants
#define BATCH 128
#define TT    512            // timesteps
#define BT    65536          // BATCH * TT
#define DIN   409            // 300 + 74 + 35
#define DPAD  416            // padded to multiple of 16
#define HD    1024           // hidden dim
#define G4    4096           // 4 * HD (gates)
#define CD    512            // fc1 output
#define OD    7              // classes

#define NCTA_REC 128         // persistent recurrence CTAs (<= 148 SMs, 1/SM)

// -------------------- scratch (static __device__, no allocs) -----------------
__device__ float g_xcat[(size_t)BT * DPAD];     // concat input, tf32-rounded
__device__ float g_Wx[(size_t)DPAD * G4];       // W_ih^T gate-interleaved, tf32
__device__ float g_bias[G4];                    // b_ih + b_hh, gate-interleaved (fp32)
__device__ float g_Wh[(size_t)HD * G4];         // W_hh^T gate-interleaved, tf32
__device__ float g_xg[(size_t)BT * G4];         // x_gates (fp32)
__device__ float g_h[2][BATCH * HD];            // double-buffered h (tf32-rounded)
__device__ float g_hall[(size_t)BT * HD];       // all h outputs (tf32-rounded)
__device__ float g_fc1T[(size_t)HD * CD];       // fc1_w^T, tf32
__device__ float g_hidden[(size_t)BT * CD];     // relu(fc1) activations (fp32)

// software grid barrier state
__device__ unsigned g_bar_count;
__device__ volatile unsigned g_bar_gen;

__device__ __forceinline__ float sigmoidf(float x) {
    return 1.0f / (1.0f + expf(-x));
}
__device__ __forceinline__ float f2tf(float x) {
    unsigned u;
    asm("cvt.rna.tf32.f32 %0, %1;" : "=r"(u) : "f"(x));
    return __uint_as_float(u);
}
__device__ __forceinline__ void mma_tf32(float c[4],
                                         unsigned a0, unsigned a1, unsigned a2, unsigned a3,
                                         unsigned b0, unsigned b1) {
    asm volatile(
        "mma.sync.aligned.m16n8k8.row.col.f32.tf32.tf32.f32 "
        "{%0,%1,%2,%3},{%4,%5,%6,%7},{%8,%9},{%0,%1,%2,%3};"
        : "+f"(c[0]), "+f"(c[1]), "+f"(c[2]), "+f"(c[3])
        : "r"(a0), "r"(a1), "r"(a2), "r"(a3), "r"(b0), "r"(b1));
}

// -------------------- input packing: concat + tf32 round + pad ---------------
__global__ void k_pack(const float* __restrict__ mt,
                       const float* __restrict__ ma,
                       const float* __restrict__ mv) {
    size_t idx = (size_t)blockIdx.x * blockDim.x + threadIdx.x;
    if (idx >= (size_t)BT * DPAD) return;
    size_t row = idx / DPAD;
    int    col = (int)(idx % DPAD);
    float v = 0.0f;
    if (col < 300)      v = mt[row * 300 + col];
    else if (col < 374) v = ma[row * 74 + (col - 300)];
    else if (col < 409) v = mv[row * 35 + (col - 374)];
    g_xcat[idx] = f2tf(v);
}

// -------------------- weight layout transforms (gate-interleaved, tf32) ------
__global__ void k_prep_wx(const float* __restrict__ W_ih) {
    int idx = blockIdx.x * blockDim.x + threadIdx.x;
    if (idx >= DPAD * G4) return;
    int k = idx / G4, n = idx % G4;
    int j = n >> 2, g = n & 3;
    g_Wx[idx] = (k < DIN) ? f2tf(W_ih[(size_t)(g * HD + j) * DIN + k]) : 0.0f;
}
__global__ void k_prep_wh(const float* __restrict__ W_hh) {
    int idx = blockIdx.x * blockDim.x + threadIdx.x;
    if (idx >= HD * G4) return;
    int k = idx / G4, n = idx % G4;
    int j = n >> 2, g = n & 3;
    g_Wh[idx] = f2tf(W_hh[(size_t)(g * HD + j) * HD + k]);
}
__global__ void k_prep_bias(const float* __restrict__ b_ih,
                            const float* __restrict__ b_hh) {
    int n = blockIdx.x * blockDim.x + threadIdx.x;
    if (n >= G4) return;
    int j = n >> 2, g = n & 3;
    g_bias[n] = b_ih[g * HD + j] + b_hh[g * HD + j];
}
__global__ void k_prep_fc1(const float* __restrict__ fc1_w) {
    int idx = blockIdx.x * blockDim.x + threadIdx.x;
    if (idx >= HD * CD) return;
    int k = idx / CD, n = idx % CD;
    g_fc1T[idx] = f2tf(fc1_w[(size_t)n * HD + k]);
}
__global__ void k_zero_state() {
    int idx = blockIdx.x * blockDim.x + threadIdx.x;
    if (idx == 0) { g_bar_count = 0; g_bar_gen = 0; }
    if (idx >= BATCH * HD) return;
    g_h[0][idx] = 0.0f;
}

// -------------------- tf32 tensor GEMM: C = A[MxK]*B[KxN] + bias (,ReLU) -----
// BM=128 BN=128 BK=16, 256 threads = 8 warps (2m x 4n), warp tile 64x32.
// A, B already tf32-rounded. M%128==0, N%128==0, K%16==0.
template <int RELU>
__global__ __launch_bounds__(256, 2) void tf32_gemm(
    const float* __restrict__ A, const float* __restrict__ B,
    float* __restrict__ C, int M, int N, int K,
    const float* __restrict__ bias) {
    __shared__ float As[128 * 20];       // [m][k], stride 20 (pad)
    __shared__ float Bs[16 * 132];       // [k][n], stride 132 (pad)
    const int tid = threadIdx.x;
    const int bm = blockIdx.y, bn = blockIdx.x;
    const int lane = tid & 31, wid = tid >> 5;
    const int gid = lane >> 2, tig = lane & 3;
    const int mbase = (wid >> 2) * 64, nbase = (wid & 3) * 32;

    float acc[4][4][4];
#pragma unroll
    for (int i = 0; i < 4; i++)
#pragma unroll
        for (int j = 0; j < 4; j++)
#pragma unroll
            for (int q = 0; q < 4; q++) acc[i][j][q] = 0.0f;

    const float* Ag = A + (size_t)bm * 128 * K;
    const float* Bg = B + (size_t)bn * 128;
    const int ar = tid >> 1, ac = (tid & 1) * 8;
    const int br = tid >> 4, bc = (tid & 15) * 8;

    for (int k0 = 0; k0 < K; k0 += 16) {
        float4 a0 = *(const float4*)(Ag + (size_t)ar * K + k0 + ac);
        float4 a1 = *(const float4*)(Ag + (size_t)ar * K + k0 + ac + 4);
        float4 b0 = *(const float4*)(Bg + (size_t)(k0 + br) * N + bc);
        float4 b1 = *(const float4*)(Bg + (size_t)(k0 + br) * N + bc + 4);
        *(float4*)&As[ar * 20 + ac]     = a0;
        *(float4*)&As[ar * 20 + ac + 4] = a1;
        *(float4*)&Bs[br * 132 + bc]     = b0;
        *(float4*)&Bs[br * 132 + bc + 4] = b1;
        __syncthreads();

#pragma unroll
        for (int kk = 0; kk < 16; kk += 8) {
            unsigned a[4][4], b[4][2];
#pragma unroll
            for (int mi = 0; mi < 4; mi++) {
                int r = mbase + mi * 16 + gid;
                a[mi][0] = __float_as_uint(As[r * 20 + kk + tig]);
                a[mi][1] = __float_as_uint(As[(r + 8) * 20 + kk + tig]);
                a[mi][2] = __float_as_uint(As[r * 20 + kk + tig + 4]);
                a[mi][3] = __float_as_uint(As[(r + 8) * 20 + kk + tig + 4]);
            }
#pragma unroll
            for (int ni = 0; ni < 4; ni++) {
                int cidx = nbase + ni * 8 + gid;
                b[ni][0] = __float_as_uint(Bs[(kk + tig) * 132 + cidx]);
                b[ni][1] = __float_as_uint(Bs[(kk + tig + 4) * 132 + cidx]);
            }
#pragma unroll
            for (int mi = 0; mi < 4; mi++)
#pragma unroll
                for (int ni = 0; ni < 4; ni++)
                    mma_tf32(acc[mi][ni], a[mi][0], a[mi][1], a[mi][2], a[mi][3],
                             b[ni][0], b[ni][1]);
        }
        __syncthreads();
    }

#pragma unroll
    for (int mi = 0; mi < 4; mi++) {
        int r = mbase + mi * 16 + gid;
#pragma unroll
        for (int ni = 0; ni < 4; ni++) {
            int cc = nbase + ni * 8 + tig * 2;
            float bb0 = bias[bn * 128 + cc];
            float bb1 = bias[bn * 128 + cc + 1];
            float v0 = acc[mi][ni][0] + bb0, v1 = acc[mi][ni][1] + bb1;
            float v2 = acc[mi][ni][2] + bb0, v3 = acc[mi][ni][3] + bb1;
            if (RELU) {
                v0 = fmaxf(v0, 0.0f); v1 = fmaxf(v1, 0.0f);
                v2 = fmaxf(v2, 0.0f); v3 = fmaxf(v3, 0.0f);
            }
            *(float2*)(C + ((size_t)bm * 128 + r) * N + bn * 128 + cc)     = make_float2(v0, v1);
            *(float2*)(C + ((size_t)bm * 128 + r + 8) * N + bn * 128 + cc) = make_float2(v2, v3);
        }
    }
}

// -------------------- persistent fused LSTM recurrence -----------------------
// 128 CTAs x 256 threads. CTA b owns gate cols [32b,32b+32) = units [8b,8b+8).
// W_hh slice pinned in smem (tf32). Cell state c lives in registers.
// Per step: C[128x32] = hprev[128x1024] @ Wh_slice, fused LSTM epilogue,
// coalesced h writes via smem staging, then software grid barrier.
#define WS_STRIDE 36                    // Ws row pad (bank-conflict-free)
#define HS_STRIDE 36                    // Hs row pad
#define WS_FLOATS (HD * WS_STRIDE)      // 36864
#define HS_FLOATS (BATCH * HS_STRIDE)   // 4608
#define REC_SMEM_BYTES ((WS_FLOATS + 2 * HS_FLOATS + BATCH * 8) * 4)

__global__ __launch_bounds__(256, 1) void lstm_persistent() {
    extern __shared__ float smem[];
    float* Ws = smem;                         // [HD][36] (cols 0..31 used)
    float* Hs = smem + WS_FLOATS;             // [2][128][36] (cols 0..31 used)
    float* h_stage = Hs + 2 * HS_FLOATS;      // [128][8]

    const int tid = threadIdx.x;
    const int lane = tid & 31, wid = tid >> 5;
    const int gid = lane >> 2, tig = lane & 3;
    const int n0 = blockIdx.x * 32;           // gate-col slice base
    const int ubase = blockIdx.x * 8;         // unit base
    const int mbase = (wid >> 1) * 32;        // warp m-tile (4 warps over m)
    const int nbase = (wid & 1) * 16;         // warp n-tile (2 warps over n)

    // load Wh slice into smem (once)
    for (int i = tid; i < HD * 8; i += 256) {
        int k = i >> 3, c4 = (i & 7) * 4;
        float4 v = *(const float4*)(g_Wh + (size_t)k * G4 + n0 + c4);
        *(float4*)&Ws[k * WS_STRIDE + c4] = v;
    }

    const int hrow = tid >> 1;                // 0..127
    const int kbase = (tid & 1) * 16;

    float c_reg[4];
#pragma unroll
    for (int i = 0; i < 4; i++) c_reg[i] = 0.0f;

    __syncthreads();   // Ws ready

    for (int t = 0; t < TT; t++) {
        const float* __restrict__ hprev = g_h[t & 1];
        float* __restrict__ hnext = g_h[(t + 1) & 1];

        float acc[2][2][4];
#pragma unroll
        for (int i = 0; i < 2; i++)
#pragma unroll
            for (int j = 0; j < 2; j++)
#pragma unroll
                for (int q = 0; q < 4; q++) acc[i][j][q] = 0.0f;

        // preload chunk 0 (L2-only loads: h changes every step, L1 is stale)
        {
            const float* src = hprev + (size_t)hrow * HD + kbase;
            float4 r0 = __ldcg((const float4*)(src));
            float4 r1 = __ldcg((const float4*)(src + 4));
            float4 r2 = __ldcg((const float4*)(src + 8));
            float4 r3 = __ldcg((const float4*)(src + 12));
            float* dst = &Hs[hrow * HS_STRIDE + kbase];
            ((float4*)dst)[0] = r0; *(float4*)(dst + 4) = r1;
            *(float4*)(dst + 8) = r2; *(float4*)(dst + 12) = r3;
        }
        __syncthreads();

        int buf = 0;
        for (int k0 = 0; k0 < HD; k0 += 32) {
            float4 nr0, nr1, nr2, nr3;
            const bool more = (k0 + 32 < HD);
            if (more) {
                const float* src = hprev + (size_t)hrow * HD + k0 + 32 + kbase;
                nr0 = __ldcg((const float4*)(src));
                nr1 = __ldcg((const float4*)(src + 4));
                nr2 = __ldcg((const float4*)(src + 8));
                nr3 = __ldcg((const float4*)(src + 12));
            }
            const float* H = Hs + buf * HS_FLOATS;
#pragma unroll
            for (int kk = 0; kk < 32; kk += 8) {
                unsigned a[2][4], b[2][2];
#pragma unroll
                for (int mi = 0; mi < 2; mi++) {
                    int r = mbase + mi * 16 + gid;
                    a[mi][0] = __float_as_uint(H[r * HS_STRIDE + kk + tig]);
                    a[mi][1] = __float_as_uint(H[(r + 8) * HS_STRIDE + kk + tig]);
                    a[mi][2] = __float_as_uint(H[r * HS_STRIDE + kk + tig + 4]);
                    a[mi][3] = __float_as_uint(H[(r + 8) * HS_STRIDE + kk + tig + 4]);
                }
#pragma unroll
                for (int ni = 0; ni < 2; ni++) {
                    int cn = nbase + ni * 8 + gid;
                    b[ni][0] = __float_as_uint(Ws[(k0 + kk + tig) * WS_STRIDE + cn]);
                    b[ni][1] = __float_as_uint(Ws[(k0 + kk + tig + 4) * WS_STRIDE + cn]);
                }
#pragma unroll
                for (int mi = 0; mi < 2; mi++)
#pragma unroll
                    for (int ni = 0; ni < 2; ni++)
                        mma_tf32(acc[mi][ni], a[mi][0], a[mi][1], a[mi][2], a[mi][3],
                                 b[ni][0], b[ni][1]);
            }
            if (more) {
                float* dst = &Hs[(buf ^ 1) * HS_FLOATS + hrow * HS_STRIDE + kbase];
                *(float4*)(dst)      = nr0; *(float4*)(dst + 4)  = nr1;
                *(float4*)(dst + 8)  = nr2; *(float4*)(dst + 12) = nr3;
            }
            __syncthreads();
            buf ^= 1;
        }

        // ---- fused LSTM epilogue ----
#pragma unroll
        for (int mi = 0; mi < 2; mi++) {
#pragma unroll
            for (int ni = 0; ni < 2; ni++) {
                float* A = acc[mi][ni];
                float p0 = __shfl_xor_sync(0xFFFFFFFFu, A[0], 1);
                float p1 = __shfl_xor_sync(0xFFFFFFFFu, A[1], 1);
                float p2 = __shfl_xor_sync(0xFFFFFFFFu, A[2], 1);
                float p3 = __shfl_xor_sync(0xFFFFFFFFu, A[3], 1);
                int row = mbase + mi * 16 + gid + ((tig & 1) ? 8 : 0);
                int lu = (nbase >> 2) + ni * 2 + (tig >> 1);
                float gi, gf, gg, go;
                if ((tig & 1) == 0) { gi = A[0]; gf = A[1]; gg = p0; go = p1; }
                else                { gi = p2;  gf = p3;  gg = A[2]; go = A[3]; }
                float4 x = *(const float4*)(g_xg + ((size_t)row * TT + t) * G4 + n0 + lu * 4);
                gi += x.x; gf += x.y; gg += x.z; go += x.w;
                float iv = sigmoidf(gi);
                float fv = sigmoidf(gf);
                float gv = tanhf(gg);
                float ov = sigmoidf(go);
                float cn = fmaf(fv, c_reg[mi * 2 + ni], iv * gv);
                c_reg[mi * 2 + ni] = cn;
                float hn = ov * tanhf(cn);
                h_stage[row * 8 + lu] = f2tf(hn);
            }
        }
        __syncthreads();

        // coalesced h writes (rows 0..127, 8 units each; 2 threads per row)
        {
            int row = tid >> 1;
            int half = (tid & 1) * 4;
            float4 v = *(float4*)&h_stage[row * 8 + half];
            *(float4*)(hnext + (size_t)row * HD + ubase + half) = v;
            *(float4*)(g_hall + ((size_t)row * TT + t) * HD + ubase + half) = v;
        }

        // ---- software grid barrier ----
        __syncthreads();
        if (tid == 0) {
            __threadfence();
            unsigned prev = atomicAdd(&g_bar_count, 1u);
            if (prev == NCTA_REC - 1) {
                g_bar_count = 0;
                __threadfence();
                g_bar_gen = (unsigned)(t + 1);
            } else {
                while (g_bar_gen < (unsigned)(t + 1)) __nanosleep(64);
            }
            __threadfence();
        }
        __syncthreads();
    }
}

// -------------------- head: fc2 (N=7) + log_softmax, warp per row ------------
__global__ __launch_bounds__(256) void head_kernel(const float* __restrict__ fc2_w,
                                                   const float* __restrict__ fc2_b,
                                                   float* __restrict__ out) {
    __shared__ float ws[OD][CD];
    const int tid = threadIdx.x;
    for (int i = tid; i < OD * CD; i += 256) ws[i / CD][i % CD] = fc2_w[i];
    __syncthreads();

    const int warp = tid >> 5, lane = tid & 31;
    size_t row = (size_t)blockIdx.x * 8 + warp;
    const float* h = g_hidden + row * CD;

    float p[OD];
#pragma unroll
    for (int o = 0; o < OD; o++) p[o] = 0.0f;

    for (int k = lane; k < CD; k += 32) {
        float hv = h[k];
#pragma unroll
        for (int o = 0; o < OD; o++) p[o] = fmaf(hv, ws[o][k], p[o]);
    }
#pragma unroll
    for (int o = 0; o < OD; o++)
#pragma unroll
        for (int s = 16; s > 0; s >>= 1)
            p[o] += __shfl_xor_sync(0xFFFFFFFFu, p[o], s);

    float z[OD], m = -1e30f;
#pragma unroll
    for (int o = 0; o < OD; o++) { z[o] = p[o] + fc2_b[o]; m = fmaxf(m, z[o]); }
    float s = 0.0f;
#pragma unroll
    for (int o = 0; o < OD; o++) s += expf(z[o] - m);
    float lse = m + logf(s);
    if (lane < OD) out[row * OD + lane] = z[lane] - lse;
}

// -------------------- launch ------------------------------------------------
extern "C" void kernel_launch(void* const* d_in, const int* in_sizes, int n_in,
                              void* d_out, int out_size) {
    const float* m_text  = (const float*)d_in[0];
    const float* m_audio = (const float*)d_in[1];
    const float* m_video = (const float*)d_in[2];
    const float* W_ih  = (const float*)d_in[5];
    const float* W_hh  = (const float*)d_in[6];
    const float* b_ih  = (const float*)d_in[7];
    const float* b_hh  = (const float*)d_in[8];
    const float* fc1_w = (const float*)d_in[9];
    const float* fc1_b = (const float*)d_in[10];
    const float* fc2_w = (const float*)d_in[11];
    const float* fc2_b = (const float*)d_in[12];
    float* out = (float*)d_out;

    float *p_xcat, *p_Wx, *p_bias, *p_xg, *p_hall, *p_fc1T, *p_hidden;
    cudaGetSymbolAddress((void**)&p_xcat,   g_xcat);
    cudaGetSymbolAddress((void**)&p_Wx,     g_Wx);
    cudaGetSymbolAddress((void**)&p_bias,   g_bias);
    cudaGetSymbolAddress((void**)&p_xg,     g_xg);
    cudaGetSymbolAddress((void**)&p_hall,   g_hall);
    cudaGetSymbolAddress((void**)&p_fc1T,   g_fc1T);
    cudaGetSymbolAddress((void**)&p_hidden, g_hidden);

    static bool attr_done = false;
    if (!attr_done) {
        cudaFuncSetAttribute(lstm_persistent,
                             cudaFuncAttributeMaxDynamicSharedMemorySize,
                             REC_SMEM_BYTES);
        attr_done = true;
    }

    // 1. pack + weight transforms (all tf32-round at producer)
    {
        size_t n = (size_t)BT * DPAD;
        k_pack<<<(unsigned)((n + 255) / 256), 256>>>(m_text, m_audio, m_video);
    }
    k_prep_wx<<<(DPAD * G4 + 255) / 256, 256>>>(W_ih);
    k_prep_wh<<<(HD * G4 + 255) / 256, 256>>>(W_hh);
    k_prep_bias<<<(G4 + 255) / 256, 256>>>(b_ih, b_hh);
    k_prep_fc1<<<(HD * CD + 255) / 256, 256>>>(fc1_w);
    k_zero_state<<<(BATCH * HD + 255) / 256, 256>>>();

    // 2. x_gates = xcat @ Wx + (b_ih + b_hh)   [65536 x 4096], tf32 tensor
    {
        dim3 grid(G4 / 128, BT / 128);
        tf32_gemm<0><<<grid, 256>>>(p_xcat, p_Wx, p_xg, BT, G4, DPAD, p_bias);
    }

    // 3. recurrence: one persistent kernel, 512 steps, software grid barrier
    lstm_persistent<<<NCTA_REC, 256, REC_SMEM_BYTES>>>();

    // 4. head: fc1 + ReLU (tf32 tensor), then fc2 + log_softmax
    {
        dim3 grid(CD / 128, BT / 128);
        tf32_gemm<1><<<grid, 256>>>(p_hall, p_fc1T, p_hidden, BT, CD, HD, fc1_b);
    }
    head_kernel<<<BT / 8, 256>>>(fc2_w, fc2_b, out);
}

// round 4
// speedup vs baseline: 3.2102x; 1.6031x over previous
#include <cuda_runtime.h>
#include <cuda_bf16.h>
#include <math.h>

// Problem constants
#define BATCH 128
#define TT    512
#define BT    65536
#define DIN   409
#define DPAD  416
#define HD    1024
#define G4    4096
#define CD    512
#define OD    7
#define NCTA_REC 128

typedef __nv_bfloat16 bf16;

// -------------------- scratch (static __device__, no allocs) -----------------
__device__ bf16  g_xcat[(size_t)BT * DPAD];   // concat input, bf16  [m][k]
__device__ bf16  g_Wx[(size_t)G4 * DPAD];     // W_ih gate-interleaved [n][k]
__device__ float g_bias[G4];                  // b_ih + b_hh, gate-interleaved
__device__ bf16  g_Wh[(size_t)G4 * HD];       // W_hh gate-interleaved [n][k]
__device__ float g_xg[(size_t)BT * G4];       // x_gates fp32 [b][t][4H]
__device__ bf16  g_h[2][BATCH * HD];          // double-buffered h (bf16)
__device__ bf16  g_hall[(size_t)BT * HD];     // all h outputs, [b*T+t][h]
__device__ bf16  g_fc1[(size_t)CD * HD];      // fc1_w bf16 [n][k]
__device__ float g_hidden[(size_t)BT * CD];   // relu(fc1) fp32

__device__ unsigned g_bar_count;
__device__ volatile unsigned g_bar_gen;

__device__ __forceinline__ float sigf(float x) {
    return 1.0f / (1.0f + __expf(-x));
}
__device__ __forceinline__ float tanhfast(float x) {
    x = fminf(fmaxf(x, -15.0f), 15.0f);
    float e = __expf(2.0f * x);
    return (e - 1.0f) * __frcp_rn(e + 1.0f);
}
__device__ __forceinline__ void mma_bf16(float c[4],
                                         unsigned a0, unsigned a1, unsigned a2, unsigned a3,
                                         unsigned b0, unsigned b1) {
    asm volatile(
        "mma.sync.aligned.m16n8k16.row.col.f32.bf16.bf16.f32 "
        "{%0,%1,%2,%3},{%4,%5,%6,%7},{%8,%9},{%0,%1,%2,%3};"
        : "+f"(c[0]), "+f"(c[1]), "+f"(c[2]), "+f"(c[3])
        : "r"(a0), "r"(a1), "r"(a2), "r"(a3), "r"(b0), "r"(b1));
}

// -------------------- pack: concat 3 modalities -> bf16, pad to 416 ----------
__global__ void k_pack(const float* __restrict__ mt,
                       const float* __restrict__ ma,
                       const float* __restrict__ mv) {
    size_t row = blockIdx.x;
    int col = threadIdx.x;          // blockDim = 416
    float v = 0.0f;
    if (col < 300)      v = mt[row * 300 + col];
    else if (col < 374) v = ma[row * 74 + (col - 300)];
    else if (col < 409) v = mv[row * 35 + (col - 374)];
    g_xcat[row * DPAD + col] = __float2bfloat16_rn(v);
}

// -------------------- fused prep: all weight transforms + state init ---------
#define N_WX   (G4 * DPAD)
#define N_WH   (G4 * HD)
#define N_FC1  (CD * HD)
#define N_ZERO (BATCH * HD)
#define N_PREP (N_WX + N_WH + G4 + N_FC1 + N_ZERO)

__global__ void k_prep_all(const float* __restrict__ W_ih,
                           const float* __restrict__ W_hh,
                           const float* __restrict__ b_ih,
                           const float* __restrict__ b_hh,
                           const float* __restrict__ fc1_w) {
    long idx = (long)blockIdx.x * 256 + threadIdx.x;
    if (idx == 0) { g_bar_count = 0; g_bar_gen = 0; }
    if (idx < N_WX) {
        int n = (int)(idx / DPAD), k = (int)(idx % DPAD);
        int j = n >> 2, g = n & 3;
        g_Wx[idx] = (k < DIN) ? __float2bfloat16_rn(W_ih[(size_t)(g * HD + j) * DIN + k])
                              : __float2bfloat16_rn(0.0f);
        return;
    }
    idx -= N_WX;
    if (idx < N_WH) {
        int n = (int)(idx / HD), k = (int)(idx % HD);
        int j = n >> 2, g = n & 3;
        g_Wh[idx] = __float2bfloat16_rn(W_hh[(size_t)(g * HD + j) * HD + k]);
        return;
    }
    idx -= N_WH;
    if (idx < G4) {
        int j = (int)(idx >> 2), g = (int)(idx & 3);
        g_bias[idx] = b_ih[g * HD + j] + b_hh[g * HD + j];
        return;
    }
    idx -= G4;
    if (idx < N_FC1) {
        g_fc1[idx] = __float2bfloat16_rn(fc1_w[idx]);
        return;
    }
    idx -= N_FC1;
    if (idx < N_ZERO) g_h[0][idx] = __float2bfloat16_rn(0.0f);
}

// -------------------- bf16 NT GEMM: C[M][N] = A[M][K] * B[N][K]^T + bias -----
// BM=128 BN=128 BK=32, 256 threads = 8 warps (2m x 4n), warp tile 64x32.
template <int RELU>
__global__ __launch_bounds__(256, 2) void bf16_gemm(
    const bf16* __restrict__ A, const bf16* __restrict__ B,
    float* __restrict__ C, int M, int N, int K,
    const float* __restrict__ bias) {
    __shared__ bf16 As[128 * 40];   // [m][k], stride 40 bf16
    __shared__ bf16 Bs[128 * 40];   // [n][k], stride 40 bf16
    const int tid = threadIdx.x;
    const int bm = blockIdx.y, bn = blockIdx.x;
    const int lane = tid & 31, wid = tid >> 5;
    const int gid = lane >> 2, tig = lane & 3;
    const int mbase = (wid >> 2) * 64, nbase = (wid & 3) * 32;

    float acc[4][4][4];
#pragma unroll
    for (int i = 0; i < 4; i++)
#pragma unroll
        for (int j = 0; j < 4; j++)
#pragma unroll
            for (int q = 0; q < 4; q++) acc[i][j][q] = 0.0f;

    const int row = tid >> 1, half = (tid & 1) * 16;
    const bf16* Aptr = A + ((size_t)bm * 128 + row) * K + half;
    const bf16* Bptr = B + ((size_t)bn * 128 + row) * K + half;

    uint4 pa0 = *(const uint4*)(Aptr);
    uint4 pa1 = *(const uint4*)(Aptr + 8);
    uint4 pb0 = *(const uint4*)(Bptr);
    uint4 pb1 = *(const uint4*)(Bptr + 8);

    for (int k0 = 0; k0 < K; k0 += 32) {
        *(uint4*)&As[row * 40 + half]     = pa0;
        *(uint4*)&As[row * 40 + half + 8] = pa1;
        *(uint4*)&Bs[row * 40 + half]     = pb0;
        *(uint4*)&Bs[row * 40 + half + 8] = pb1;
        __syncthreads();

        if (k0 + 32 < K) {
            pa0 = *(const uint4*)(Aptr + k0 + 32);
            pa1 = *(const uint4*)(Aptr + k0 + 40);
            pb0 = *(const uint4*)(Bptr + k0 + 32);
            pb1 = *(const uint4*)(Bptr + k0 + 40);
        }

#pragma unroll
        for (int kk = 0; kk < 32; kk += 16) {
            unsigned a[4][4], b[4][2];
#pragma unroll
            for (int mi = 0; mi < 4; mi++) {
                int r = mbase + mi * 16 + gid;
                a[mi][0] = *(const unsigned*)&As[r * 40 + kk + 2 * tig];
                a[mi][1] = *(const unsigned*)&As[(r + 8) * 40 + kk + 2 * tig];
                a[mi][2] = *(const unsigned*)&As[r * 40 + kk + 2 * tig + 8];
                a[mi][3] = *(const unsigned*)&As[(r + 8) * 40 + kk + 2 * tig + 8];
            }
#pragma unroll
            for (int ni = 0; ni < 4; ni++) {
                int cn = nbase + ni * 8 + gid;
                b[ni][0] = *(const unsigned*)&Bs[cn * 40 + kk + 2 * tig];
                b[ni][1] = *(const unsigned*)&Bs[cn * 40 + kk + 2 * tig + 8];
            }
#pragma unroll
            for (int mi = 0; mi < 4; mi++)
#pragma unroll
                for (int ni = 0; ni < 4; ni++)
                    mma_bf16(acc[mi][ni], a[mi][0], a[mi][1], a[mi][2], a[mi][3],
                             b[ni][0], b[ni][1]);
        }
        __syncthreads();
    }

#pragma unroll
    for (int mi = 0; mi < 4; mi++) {
        int r = mbase + mi * 16 + gid;
#pragma unroll
        for (int ni = 0; ni < 4; ni++) {
            int cc = nbase + ni * 8 + tig * 2;
            float bb0 = bias[bn * 128 + cc];
            float bb1 = bias[bn * 128 + cc + 1];
            float v0 = acc[mi][ni][0] + bb0, v1 = acc[mi][ni][1] + bb1;
            float v2 = acc[mi][ni][2] + bb0, v3 = acc[mi][ni][3] + bb1;
            if (RELU) {
                v0 = fmaxf(v0, 0.0f); v1 = fmaxf(v1, 0.0f);
                v2 = fmaxf(v2, 0.0f); v3 = fmaxf(v3, 0.0f);
            }
            *(float2*)(C + ((size_t)bm * 128 + r) * N + bn * 128 + cc)     = make_float2(v0, v1);
            *(float2*)(C + ((size_t)bm * 128 + r + 8) * N + bn * 128 + cc) = make_float2(v2, v3);
        }
    }
}

// -------------------- persistent fused LSTM recurrence (bf16 MMA) ------------
// 128 CTAs x 256 threads; CTA b owns gate cols [32b,32b+32) = units [8b,8b+8).
// Wh slice (32 x 1024 bf16) pinned in smem; c state in registers.
#define WS_STRIDE 1032                     // bf16 elements per Ws col row
#define HS_STRIDE 40
#define WS_ELE (32 * WS_STRIDE)            // 33024
#define HS_ELE (BATCH * HS_STRIDE)         // 5120
#define REC_SMEM_BYTES ((WS_ELE + 2 * HS_ELE + BATCH * 8) * 2)

__global__ __launch_bounds__(256, 1) void lstm_persistent() {
    extern __shared__ bf16 smem[];
    bf16* Ws = smem;                       // [32 col][1032]
    bf16* Hs = smem + WS_ELE;              // [2][128][40]
    bf16* h_stage = Hs + 2 * HS_ELE;       // [128][8]

    const int tid = threadIdx.x;
    const int lane = tid & 31, wid = tid >> 5;
    const int gid = lane >> 2, tig = lane & 3;
    const int n0 = blockIdx.x * 32;
    const int ubase = blockIdx.x * 8;
    const int mbase = (wid >> 1) * 32;     // 4 warps over m=128
    const int nbase = (wid & 1) * 16;      // 2 warps over n=32

    // load Wh slice (once): 32 cols x 1024 k
    for (int i = tid; i < 32 * 128; i += 256) {
        int c = i >> 7, kv = (i & 127) * 8;
        *(uint4*)&Ws[c * WS_STRIDE + kv] =
            *(const uint4*)&g_Wh[(size_t)(n0 + c) * HD + kv];
    }

    const int hrow = tid >> 1;
    const int khalf = (tid & 1) * 16;

    float c_reg[4];
#pragma unroll
    for (int i = 0; i < 4; i++) c_reg[i] = 0.0f;

    // per-thread epilogue coordinates (fixed across steps)
    int ep_row[2][2], ep_lu[2][2];
#pragma unroll
    for (int mi = 0; mi < 2; mi++)
#pragma unroll
        for (int ni = 0; ni < 2; ni++) {
            ep_row[mi][ni] = mbase + mi * 16 + gid + ((tig & 1) ? 8 : 0);
            ep_lu[mi][ni] = (nbase >> 2) + ni * 2 + (tig >> 1);
        }

    __syncthreads();   // Ws ready

    for (int t = 0; t < TT; t++) {
        const bf16* __restrict__ hprev = g_h[t & 1];
        bf16* __restrict__ hnext = g_h[(t + 1) & 1];

        float acc[2][2][4];
#pragma unroll
        for (int i = 0; i < 2; i++)
#pragma unroll
            for (int j = 0; j < 2; j++)
#pragma unroll
                for (int q = 0; q < 4; q++) acc[i][j][q] = 0.0f;

        // prefetch x_gates for this step (DRAM latency hidden behind GEMM)
        float4 xg[2][2];
#pragma unroll
        for (int mi = 0; mi < 2; mi++)
#pragma unroll
            for (int ni = 0; ni < 2; ni++)
                xg[mi][ni] = *(const float4*)(g_xg +
                    ((size_t)ep_row[mi][ni] * TT + t) * G4 + n0 + ep_lu[mi][ni] * 4);

        // preload h chunk 0 (L2-only: h written by other SMs each step)
        {
            const bf16* src = hprev + (size_t)hrow * HD + khalf;
            uint4 h0 = __ldcg((const uint4*)(src));
            uint4 h1 = __ldcg((const uint4*)(src + 8));
            *(uint4*)&Hs[hrow * HS_STRIDE + khalf]     = h0;
            *(uint4*)&Hs[hrow * HS_STRIDE + khalf + 8] = h1;
        }
        __syncthreads();

        int buf = 0;
        for (int k0 = 0; k0 < HD; k0 += 32) {
            uint4 nh0, nh1;
            const bool more = (k0 + 32 < HD);
            if (more) {
                const bf16* src = hprev + (size_t)hrow * HD + k0 + 32 + khalf;
                nh0 = __ldcg((const uint4*)(src));
                nh1 = __ldcg((const uint4*)(src + 8));
            }
            const bf16* H = Hs + buf * HS_ELE;
#pragma unroll
            for (int kk = 0; kk < 32; kk += 16) {
                unsigned a[2][4], b[2][2];
#pragma unroll
                for (int mi = 0; mi < 2; mi++) {
                    int r = mbase + mi * 16 + gid;
                    a[mi][0] = *(const unsigned*)&H[r * HS_STRIDE + kk + 2 * tig];
                    a[mi][1] = *(const unsigned*)&H[(r + 8) * HS_STRIDE + kk + 2 * tig];
                    a[mi][2] = *(const unsigned*)&H[r * HS_STRIDE + kk + 2 * tig + 8];
                    a[mi][3] = *(const unsigned*)&H[(r + 8) * HS_STRIDE + kk + 2 * tig + 8];
                }
#pragma unroll
                for (int ni = 0; ni < 2; ni++) {
                    int cn = nbase + ni * 8 + gid;
                    b[ni][0] = *(const unsigned*)&Ws[cn * WS_STRIDE + k0 + kk + 2 * tig];
                    b[ni][1] = *(const unsigned*)&Ws[cn * WS_STRIDE + k0 + kk + 2 * tig + 8];
                }
#pragma unroll
                for (int mi = 0; mi < 2; mi++)
#pragma unroll
                    for (int ni = 0; ni < 2; ni++)
                        mma_bf16(acc[mi][ni], a[mi][0], a[mi][1], a[mi][2], a[mi][3],
                                 b[ni][0], b[ni][1]);
            }
            if (more) {
                bf16* dst = &Hs[(buf ^ 1) * HS_ELE + hrow * HS_STRIDE + khalf];
                *(uint4*)(dst)     = nh0;
                *(uint4*)(dst + 8) = nh1;
            }
            __syncthreads();
            buf ^= 1;
        }

        // ---- fused LSTM epilogue ----
#pragma unroll
        for (int mi = 0; mi < 2; mi++) {
#pragma unroll
            for (int ni = 0; ni < 2; ni++) {
                float* A = acc[mi][ni];
                float p0 = __shfl_xor_sync(0xFFFFFFFFu, A[0], 1);
                float p1 = __shfl_xor_sync(0xFFFFFFFFu, A[1], 1);
                float p2 = __shfl_xor_sync(0xFFFFFFFFu, A[2], 1);
                float p3 = __shfl_xor_sync(0xFFFFFFFFu, A[3], 1);
                float gi, gf, gg, go;
                if ((tig & 1) == 0) { gi = A[0]; gf = A[1]; gg = p0; go = p1; }
                else                { gi = p2;  gf = p3;  gg = A[2]; go = A[3]; }
                float4 x = xg[mi][ni];
                gi += x.x; gf += x.y; gg += x.z; go += x.w;
                float iv = sigf(gi);
                float fv = sigf(gf);
                float gv = tanhfast(gg);
                float ov = sigf(go);
                float cn = fmaf(fv, c_reg[mi * 2 + ni], iv * gv);
                c_reg[mi * 2 + ni] = cn;
                float hn = ov * tanhfast(cn);
                h_stage[ep_row[mi][ni] * 8 + ep_lu[mi][ni]] = __float2bfloat16_rn(hn);
            }
        }
        __syncthreads();

        // coalesced h writes: 128 threads, one uint4 (8 bf16) per batch row
        if (tid < 128) {
            uint4 v = *(uint4*)&h_stage[tid * 8];
            *(uint4*)(hnext + (size_t)tid * HD + ubase) = v;
            *(uint4*)(g_hall + ((size_t)tid * TT + t) * HD + ubase) = v;
        }

        // ---- software grid barrier ----
        __syncthreads();
        if (tid == 0) {
            __threadfence();
            unsigned prev = atomicAdd(&g_bar_count, 1u);
            if (prev == NCTA_REC - 1) {
                g_bar_count = 0;
                __threadfence();
                g_bar_gen = (unsigned)(t + 1);
            } else {
                while (g_bar_gen < (unsigned)(t + 1)) __nanosleep(32);
            }
            __threadfence();
        }
        __syncthreads();
    }
}

// -------------------- head: fc2 (N=7) + log_softmax, warp per row ------------
__global__ __launch_bounds__(256) void head_kernel(const float* __restrict__ fc2_w,
                                                   const float* __restrict__ fc2_b,
                                                   float* __restrict__ out) {
    __shared__ float ws[OD][CD];
    const int tid = threadIdx.x;
    for (int i = tid; i < OD * CD; i += 256) ws[i / CD][i % CD] = fc2_w[i];
    __syncthreads();

    const int warp = tid >> 5, lane = tid & 31;
    size_t row = (size_t)blockIdx.x * 8 + warp;
    const float* h = g_hidden + row * CD;

    float p[OD];
#pragma unroll
    for (int o = 0; o < OD; o++) p[o] = 0.0f;

    for (int k = lane; k < CD; k += 32) {
        float hv = h[k];
#pragma unroll
        for (int o = 0; o < OD; o++) p[o] = fmaf(hv, ws[o][k], p[o]);
    }
#pragma unroll
    for (int o = 0; o < OD; o++)
#pragma unroll
        for (int s = 16; s > 0; s >>= 1)
            p[o] += __shfl_xor_sync(0xFFFFFFFFu, p[o], s);

    float z[OD], m = -1e30f;
#pragma unroll
    for (int o = 0; o < OD; o++) { z[o] = p[o] + fc2_b[o]; m = fmaxf(m, z[o]); }
    float s = 0.0f;
#pragma unroll
    for (int o = 0; o < OD; o++) s += expf(z[o] - m);
    float lse = m + logf(s);
    if (lane < OD) out[row * OD + lane] = z[lane] - lse;
}

// -------------------- launch ------------------------------------------------
extern "C" void kernel_launch(void* const* d_in, const int* in_sizes, int n_in,
                              void* d_out, int out_size) {
    const float* m_text  = (const float*)d_in[0];
    const float* m_audio = (const float*)d_in[1];
    const float* m_video = (const float*)d_in[2];
    const float* W_ih  = (const float*)d_in[5];
    const float* W_hh  = (const float*)d_in[6];
    const float* b_ih  = (const float*)d_in[7];
    const float* b_hh  = (const float*)d_in[8];
    const float* fc1_w = (const float*)d_in[9];
    const float* fc1_b = (const float*)d_in[10];
    const float* fc2_w = (const float*)d_in[11];
    const float* fc2_b = (const float*)d_in[12];
    float* out = (float*)d_out;

    bf16 *p_xcat, *p_Wx, *p_Wh, *p_hall, *p_fc1;
    float *p_bias, *p_xg, *p_hidden;
    cudaGetSymbolAddress((void**)&p_xcat,   g_xcat);
    cudaGetSymbolAddress((void**)&p_Wx,     g_Wx);
    cudaGetSymbolAddress((void**)&p_Wh,     g_Wh);
    cudaGetSymbolAddress((void**)&p_bias,   g_bias);
    cudaGetSymbolAddress((void**)&p_xg,     g_xg);
    cudaGetSymbolAddress((void**)&p_hall,   g_hall);
    cudaGetSymbolAddress((void**)&p_fc1,    g_fc1);
    cudaGetSymbolAddress((void**)&p_hidden, g_hidden);

    static bool attr_done = false;
    if (!attr_done) {
        cudaFuncSetAttribute(lstm_persistent,
                             cudaFuncAttributeMaxDynamicSharedMemorySize,
                             REC_SMEM_BYTES);
        attr_done = true;
    }

    // launch 0: pack (concat -> bf16)
    k_pack<<<BT, DPAD>>>(m_text, m_audio, m_video);
    // launch 1: all weight prep + state init
    k_prep_all<<<(N_PREP + 255) / 256, 256>>>(W_ih, W_hh, b_ih, b_hh, fc1_w);
    // launch 2: x_gates = xcat @ Wx^T + bias   [65536 x 4096] bf16 tensor
    {
        dim3 grid(G4 / 128, BT / 128);
        bf16_gemm<0><<<grid, 256>>>(p_xcat, p_Wx, p_xg, BT, G4, DPAD, p_bias);
    }
    // launch 3: persistent LSTM recurrence (512 steps)
    lstm_persistent<<<NCTA_REC, 256, REC_SMEM_BYTES>>>();
    // launch 4: fc1 + ReLU  [65536 x 512] bf16 tensor
    {
        dim3 grid(CD / 128, BT / 128);
        bf16_gemm<1><<<grid, 256>>>(p_hall, p_fc1, p_hidden, BT, CD, HD, fc1_b);
    }
    // launch 5: fc2 + log_softmax
    head_kernel<<<BT / 8, 256>>>(fc2_w, fc2_b, out);
}

// round 9
// speedup vs baseline: 4.6945x; 1.4623x over previous
#include <cuda_runtime.h>
#include <cuda_bf16.h>
#include <math.h>

// Problem constants
#define BATCH 128
#define TT    512
#define BT    65536
#define DIN   409
#define DPAD  416
#define HD    1024
#define G4    4096
#define CD    512
#define OD    7
#define NCTA_REC 128

typedef __nv_bfloat16 bf16;

// -------------------- scratch (static __device__, no allocs) -----------------
__device__ bf16  g_xcat[(size_t)BT * DPAD];   // concat input bf16 [m][k]
__device__ bf16  g_Wx[(size_t)G4 * DPAD];     // W_ih gate-interleaved [n][k]
__device__ float g_bias[G4];                  // b_ih + b_hh gate-interleaved
__device__ bf16  g_Wh[(size_t)G4 * HD];       // W_hh gate-interleaved [n][k]
__device__ float g_xg[(size_t)BT * G4];       // x_gates fp32 [b][t][4H]
__device__ bf16  g_h[2][BATCH * HD];          // double-buffered h
__device__ bf16  g_hall[(size_t)BT * HD];     // all h outputs [b*T+t][h]
__device__ bf16  g_fc1[(size_t)CD * HD];      // fc1_w bf16 [n][k]
__device__ float g_hidden[(size_t)BT * CD];   // relu(fc1) fp32

__device__ unsigned g_bar_count;
__device__ volatile unsigned g_bar_gen;

__device__ __forceinline__ float sigf(float x) {
    return 1.0f / (1.0f + __expf(-x));
}
__device__ __forceinline__ float tanhfast(float x) {
    x = fminf(fmaxf(x, -15.0f), 15.0f);
    float e = __expf(2.0f * x);
    return (e - 1.0f) * __frcp_rn(e + 1.0f);
}
__device__ __forceinline__ void mma_bf16(float c[4],
                                         unsigned a0, unsigned a1, unsigned a2, unsigned a3,
                                         unsigned b0, unsigned b1) {
    asm volatile(
        "mma.sync.aligned.m16n8k16.row.col.f32.bf16.bf16.f32 "
        "{%0,%1,%2,%3},{%4,%5,%6,%7},{%8,%9},{%0,%1,%2,%3};"
        : "+f"(c[0]), "+f"(c[1]), "+f"(c[2]), "+f"(c[3])
        : "r"(a0), "r"(a1), "r"(a2), "r"(a3), "r"(b0), "r"(b1));
}
__device__ __forceinline__ void ldsm_x4(unsigned& r0, unsigned& r1,
                                        unsigned& r2, unsigned& r3, unsigned addr) {
    asm volatile("ldmatrix.sync.aligned.m8n8.x4.shared.b16 {%0,%1,%2,%3}, [%4];"
                 : "=r"(r0), "=r"(r1), "=r"(r2), "=r"(r3) : "r"(addr));
}
__device__ __forceinline__ void cp16(unsigned smem_addr, const void* gptr) {
    asm volatile("cp.async.cg.shared.global [%0], [%1], 16;"
                 :: "r"(smem_addr), "l"(gptr));
}
__device__ __forceinline__ void cp_commit() {
    asm volatile("cp.async.commit_group;");
}
__device__ __forceinline__ void cp_wait0() {
    asm volatile("cp.async.wait_group 0;");
}

// -------------------- pack: concat -> bf16, pad to 416 -----------------------
__global__ void k_pack(const float* __restrict__ mt,
                       const float* __restrict__ ma,
                       const float* __restrict__ mv) {
    size_t row = blockIdx.x;
    int col = threadIdx.x;          // blockDim = 416
    float v = 0.0f;
    if (col < 300)      v = mt[row * 300 + col];
    else if (col < 374) v = ma[row * 74 + (col - 300)];
    else if (col < 409) v = mv[row * 35 + (col - 374)];
    g_xcat[row * DPAD + col] = __float2bfloat16_rn(v);
}

// -------------------- fused prep ---------------------------------------------
#define N_WX   (G4 * DPAD)
#define N_WH   (G4 * HD)
#define N_FC1  (CD * HD)
#define N_ZERO (BATCH * HD)
#define N_PREP (N_WX + N_WH + G4 + N_FC1 + N_ZERO)

__global__ void k_prep_all(const float* __restrict__ W_ih,
                           const float* __restrict__ W_hh,
                           const float* __restrict__ b_ih,
                           const float* __restrict__ b_hh,
                           const float* __restrict__ fc1_w) {
    long idx = (long)blockIdx.x * 256 + threadIdx.x;
    if (idx == 0) { g_bar_count = 0; g_bar_gen = 0; }
    if (idx < N_WX) {
        int n = (int)(idx / DPAD), k = (int)(idx % DPAD);
        int j = n >> 2, g = n & 3;
        g_Wx[idx] = (k < DIN) ? __float2bfloat16_rn(W_ih[(size_t)(g * HD + j) * DIN + k])
                              : __float2bfloat16_rn(0.0f);
        return;
    }
    idx -= N_WX;
    if (idx < N_WH) {
        int n = (int)(idx / HD), k = (int)(idx % HD);
        int j = n >> 2, g = n & 3;
        g_Wh[idx] = __float2bfloat16_rn(W_hh[(size_t)(g * HD + j) * HD + k]);
        return;
    }
    idx -= N_WH;
    if (idx < G4) {
        int j = (int)(idx >> 2), g = (int)(idx & 3);
        g_bias[idx] = b_ih[g * HD + j] + b_hh[g * HD + j];
        return;
    }
    idx -= G4;
    if (idx < N_FC1) {
        g_fc1[idx] = __float2bfloat16_rn(fc1_w[idx]);
        return;
    }
    idx -= N_FC1;
    if (idx < N_ZERO) g_h[0][idx] = __float2bfloat16_rn(0.0f);
}

// -------------------- bf16 NT GEMM: C[M][N] = A[M][K]*B[N][K]^T + bias -------
template <int RELU>
__global__ __launch_bounds__(256, 2) void bf16_gemm(
    const bf16* __restrict__ A, const bf16* __restrict__ B,
    float* __restrict__ C, int M, int N, int K,
    const float* __restrict__ bias) {
    __shared__ bf16 As[128 * 40];
    __shared__ bf16 Bs[128 * 40];
    const int tid = threadIdx.x;
    const int bm = blockIdx.y, bn = blockIdx.x;
    const int lane = tid & 31, wid = tid >> 5;
    const int gid = lane >> 2, tig = lane & 3;
    const int mbase = (wid >> 2) * 64, nbase = (wid & 3) * 32;

    float acc[4][4][4];
#pragma unroll
    for (int i = 0; i < 4; i++)
#pragma unroll
        for (int j = 0; j < 4; j++)
#pragma unroll
            for (int q = 0; q < 4; q++) acc[i][j][q] = 0.0f;

    const int row = tid >> 1, half = (tid & 1) * 16;
    const bf16* Aptr = A + ((size_t)bm * 128 + row) * K + half;
    const bf16* Bptr = B + ((size_t)bn * 128 + row) * K + half;

    uint4 pa0 = *(const uint4*)(Aptr);
    uint4 pa1 = *(const uint4*)(Aptr + 8);
    uint4 pb0 = *(const uint4*)(Bptr);
    uint4 pb1 = *(const uint4*)(Bptr + 8);

    for (int k0 = 0; k0 < K; k0 += 32) {
        *(uint4*)&As[row * 40 + half]     = pa0;
        *(uint4*)&As[row * 40 + half + 8] = pa1;
        *(uint4*)&Bs[row * 40 + half]     = pb0;
        *(uint4*)&Bs[row * 40 + half + 8] = pb1;
        __syncthreads();

        if (k0 + 32 < K) {
            pa0 = *(const uint4*)(Aptr + k0 + 32);
            pa1 = *(const uint4*)(Aptr + k0 + 40);
            pb0 = *(const uint4*)(Bptr + k0 + 32);
            pb1 = *(const uint4*)(Bptr + k0 + 40);
        }

#pragma unroll
        for (int kk = 0; kk < 32; kk += 16) {
            unsigned a[4][4], b[4][2];
#pragma unroll
            for (int mi = 0; mi < 4; mi++) {
                int r = mbase + mi * 16 + gid;
                a[mi][0] = *(const unsigned*)&As[r * 40 + kk + 2 * tig];
                a[mi][1] = *(const unsigned*)&As[(r + 8) * 40 + kk + 2 * tig];
                a[mi][2] = *(const unsigned*)&As[r * 40 + kk + 2 * tig + 8];
                a[mi][3] = *(const unsigned*)&As[(r + 8) * 40 + kk + 2 * tig + 8];
            }
#pragma unroll
            for (int ni = 0; ni < 4; ni++) {
                int cn = nbase + ni * 8 + gid;
                b[ni][0] = *(const unsigned*)&Bs[cn * 40 + kk + 2 * tig];
                b[ni][1] = *(const unsigned*)&Bs[cn * 40 + kk + 2 * tig + 8];
            }
#pragma unroll
            for (int mi = 0; mi < 4; mi++)
#pragma unroll
                for (int ni = 0; ni < 4; ni++)
                    mma_bf16(acc[mi][ni], a[mi][0], a[mi][1], a[mi][2], a[mi][3],
                             b[ni][0], b[ni][1]);
        }
        __syncthreads();
    }

#pragma unroll
    for (int mi = 0; mi < 4; mi++) {
        int r = mbase + mi * 16 + gid;
#pragma unroll
        for (int ni = 0; ni < 4; ni++) {
            int cc = nbase + ni * 8 + tig * 2;
            float bb0 = bias[bn * 128 + cc];
            float bb1 = bias[bn * 128 + cc + 1];
            float v0 = acc[mi][ni][0] + bb0, v1 = acc[mi][ni][1] + bb1;
            float v2 = acc[mi][ni][2] + bb0, v3 = acc[mi][ni][3] + bb1;
            if (RELU) {
                v0 = fmaxf(v0, 0.0f); v1 = fmaxf(v1, 0.0f);
                v2 = fmaxf(v2, 0.0f); v3 = fmaxf(v3, 0.0f);
            }
            *(float2*)(C + ((size_t)bm * 128 + r) * N + bn * 128 + cc)     = make_float2(v0, v1);
            *(float2*)(C + ((size_t)bm * 128 + r + 8) * N + bn * 128 + cc) = make_float2(v2, v3);
        }
    }
}

// -------------------- persistent fused LSTM recurrence -----------------------
// 128 CTAs x 256 threads; CTA b owns gate cols [32b,32b+32) = units [8b,8b+8).
// ldmatrix fragment feeds + cp.async.cg h tiles + K-chunk 128.
#define WS_STRIDE 1032                       // bf16 per Ws row (32 rows)
#define HS_STRIDE 136                        // 128 + 8 pad
#define KCHUNK 128
#define NCHUNK (HD / KCHUNK)                 // 8
#define WS_ELE (32 * WS_STRIDE)              // 33024
#define HS_ELE (BATCH * HS_STRIDE)           // 17408 per buffer
#define REC_SMEM_BYTES ((WS_ELE + 2 * HS_ELE + BATCH * 8) * 2)

__global__ __launch_bounds__(256, 1) void lstm_persistent() {
    extern __shared__ bf16 smem[];
    bf16* Ws = smem;                         // [32][1032]
    bf16* Hs = smem + WS_ELE;                // [2][128][136]
    bf16* h_stage = Hs + 2 * HS_ELE;         // [128][8]

    const int tid = threadIdx.x;
    const int lane = tid & 31, wid = tid >> 5;
    const int gid = lane >> 2, tig = lane & 3;
    const int lrow = lane & 7, lmat = lane >> 3;
    const int n0 = blockIdx.x * 32;
    const int ubase = blockIdx.x * 8;
    const int mbase = (wid >> 1) * 32;       // 4 warps over m=128
    const int nbase = (wid & 1) * 16;        // 2 warps over n=32

    const unsigned ws_u32 = (unsigned)__cvta_generic_to_shared(Ws);
    const unsigned hs_u32 = (unsigned)__cvta_generic_to_shared(Hs);

    // load Wh slice once: 32 cols x 1024 k
    for (int i = tid; i < 32 * 128; i += 256) {
        int c = i >> 7, kv = (i & 127) * 8;
        *(uint4*)&Ws[c * WS_STRIDE + kv] =
            *(const uint4*)&g_Wh[(size_t)(n0 + c) * HD + kv];
    }

    // ldmatrix row bases (element offsets), fixed across steps
    int a_eoff[2];
#pragma unroll
    for (int mi = 0; mi < 2; mi++)
        a_eoff[mi] = (mbase + mi * 16 + (lmat & 1) * 8 + lrow) * HS_STRIDE + (lmat >> 1) * 8;
    const int b_eoff = (nbase + (lmat >> 1) * 8 + lrow) * WS_STRIDE + (lmat & 1) * 8;

    float c_reg[4];
#pragma unroll
    for (int i = 0; i < 4; i++) c_reg[i] = 0.0f;

    int ep_row[2][2], ep_lu[2][2];
#pragma unroll
    for (int mi = 0; mi < 2; mi++)
#pragma unroll
        for (int ni = 0; ni < 2; ni++) {
            ep_row[mi][ni] = mbase + mi * 16 + gid + ((tig & 1) ? 8 : 0);
            ep_lu[mi][ni] = (nbase >> 2) + ni * 2 + (tig >> 1);
        }

    __syncthreads();   // Ws ready

    for (int t = 0; t < TT; t++) {
        const bf16* __restrict__ hprev = g_h[t & 1];
        bf16* __restrict__ hnext = g_h[(t + 1) & 1];

        float acc[2][2][4];
#pragma unroll
        for (int i = 0; i < 2; i++)
#pragma unroll
            for (int j = 0; j < 2; j++)
#pragma unroll
                for (int q = 0; q < 4; q++) acc[i][j][q] = 0.0f;

        // prefetch x_gates (DRAM) into registers
        float4 xg[2][2];
#pragma unroll
        for (int mi = 0; mi < 2; mi++)
#pragma unroll
            for (int ni = 0; ni < 2; ni++)
                xg[mi][ni] = *(const float4*)(g_xg +
                    ((size_t)ep_row[mi][ni] * TT + t) * G4 + n0 + ep_lu[mi][ni] * 4);

        // preload chunk 0 via cp.async (L2-only)
#pragma unroll
        for (int r = 0; r < 8; r++) {
            int c = tid + r * 256;
            int row = c >> 4, k16 = c & 15;
            cp16(hs_u32 + (unsigned)(row * HS_STRIDE + k16 * 8) * 2,
                 hprev + (size_t)row * HD + k16 * 8);
        }
        cp_commit();
        cp_wait0();
        __syncthreads();

        int buf = 0;
        for (int ch = 0; ch < NCHUNK; ch++) {
            const int k0 = ch * KCHUNK;
            if (ch + 1 < NCHUNK) {
                const unsigned dstb = hs_u32 + (unsigned)((buf ^ 1) * HS_ELE) * 2;
#pragma unroll
                for (int r = 0; r < 8; r++) {
                    int c = tid + r * 256;
                    int row = c >> 4, k16 = c & 15;
                    cp16(dstb + (unsigned)(row * HS_STRIDE + k16 * 8) * 2,
                         hprev + (size_t)row * HD + k0 + KCHUNK + k16 * 8);
                }
                cp_commit();
            }

            const unsigned hb = hs_u32 + (unsigned)(buf * HS_ELE) * 2;
#pragma unroll
            for (int kk = 0; kk < KCHUNK; kk += 16) {
                unsigned a[2][4], b[4];
                ldsm_x4(a[0][0], a[0][1], a[0][2], a[0][3],
                        hb + (unsigned)(a_eoff[0] + kk) * 2);
                ldsm_x4(a[1][0], a[1][1], a[1][2], a[1][3],
                        hb + (unsigned)(a_eoff[1] + kk) * 2);
                ldsm_x4(b[0], b[1], b[2], b[3],
                        ws_u32 + (unsigned)(b_eoff + k0 + kk) * 2);
#pragma unroll
                for (int mi = 0; mi < 2; mi++) {
                    mma_bf16(acc[mi][0], a[mi][0], a[mi][1], a[mi][2], a[mi][3],
                             b[0], b[1]);
                    mma_bf16(acc[mi][1], a[mi][0], a[mi][1], a[mi][2], a[mi][3],
                             b[2], b[3]);
                }
            }
            if (ch + 1 < NCHUNK) cp_wait0();
            __syncthreads();
            buf ^= 1;
        }

        // ---- fused LSTM epilogue ----
#pragma unroll
        for (int mi = 0; mi < 2; mi++) {
#pragma unroll
            for (int ni = 0; ni < 2; ni++) {
                float* A = acc[mi][ni];
                float p0 = __shfl_xor_sync(0xFFFFFFFFu, A[0], 1);
                float p1 = __shfl_xor_sync(0xFFFFFFFFu, A[1], 1);
                float p2 = __shfl_xor_sync(0xFFFFFFFFu, A[2], 1);
                float p3 = __shfl_xor_sync(0xFFFFFFFFu, A[3], 1);
                float gi, gf, gg, go;
                if ((tig & 1) == 0) { gi = A[0]; gf = A[1]; gg = p0; go = p1; }
                else                { gi = p2;  gf = p3;  gg = A[2]; go = A[3]; }
                float4 x = xg[mi][ni];
                gi += x.x; gf += x.y; gg += x.z; go += x.w;
                float iv = sigf(gi);
                float fv = sigf(gf);
                float gv = tanhfast(gg);
                float ov = sigf(go);
                float cn = fmaf(fv, c_reg[mi * 2 + ni], iv * gv);
                c_reg[mi * 2 + ni] = cn;
                float hn = ov * tanhfast(cn);
                h_stage[ep_row[mi][ni] * 8 + ep_lu[mi][ni]] = __float2bfloat16_rn(hn);
            }
        }
        __syncthreads();

        // coalesced h writes
        if (tid < 128) {
            uint4 v = *(uint4*)&h_stage[tid * 8];
            *(uint4*)(hnext + (size_t)tid * HD + ubase) = v;
            *(uint4*)(g_hall + ((size_t)tid * TT + t) * HD + ubase) = v;
        }

        // ---- software grid barrier (all threads fence: orders every
        //      thread's hnext stores before the arrive, not just tid 0's) ----
        __threadfence();
        __syncthreads();
        if (tid == 0) {
            unsigned prev = atomicAdd(&g_bar_count, 1u);
            if (prev == NCTA_REC - 1) {
                g_bar_count = 0;
                __threadfence();
                g_bar_gen = (unsigned)(t + 1);
            } else {
                while (g_bar_gen < (unsigned)(t + 1)) __nanosleep(32);
            }
            __threadfence();
        }
        __syncthreads();
    }
}

// -------------------- head: fc2 (N=7) + log_softmax --------------------------
__global__ __launch_bounds__(256) void head_kernel(const float* __restrict__ fc2_w,
                                                   const float* __restrict__ fc2_b,
                                                   float* __restrict__ out) {
    __shared__ float ws[OD][CD];
    const int tid = threadIdx.x;
    for (int i = tid; i < OD * CD; i += 256) ws[i / CD][i % CD] = fc2_w[i];
    __syncthreads();

    const int warp = tid >> 5, lane = tid & 31;
    size_t row = (size_t)blockIdx.x * 8 + warp;
    const float* h = g_hidden + row * CD;

    float p[OD];
#pragma unroll
    for (int o = 0; o < OD; o++) p[o] = 0.0f;

    for (int k = lane; k < CD; k += 32) {
        float hv = h[k];
#pragma unroll
        for (int o = 0; o < OD; o++) p[o] = fmaf(hv, ws[o][k], p[o]);
    }
#pragma unroll
    for (int o = 0; o < OD; o++)
#pragma unroll
        for (int s = 16; s > 0; s >>= 1)
            p[o] += __shfl_xor_sync(0xFFFFFFFFu, p[o], s);

    float z[OD], m = -1e30f;
#pragma unroll
    for (int o = 0; o < OD; o++) { z[o] = p[o] + fc2_b[o]; m = fmaxf(m, z[o]); }
    float s = 0.0f;
#pragma unroll
    for (int o = 0; o < OD; o++) s += expf(z[o] - m);
    float lse = m + logf(s);
    if (lane < OD) out[row * OD + lane] = z[lane] - lse;
}

// -------------------- launch ------------------------------------------------
extern "C" void kernel_launch(void* const* d_in, const int* in_sizes, int n_in,
                              void* d_out, int out_size) {
    const float* m_text  = (const float*)d_in[0];
    const float* m_audio = (const float*)d_in[1];
    const float* m_video = (const float*)d_in[2];
    const float* W_ih  = (const float*)d_in[5];
    const float* W_hh  = (const float*)d_in[6];
    const float* b_ih  = (const float*)d_in[7];
    const float* b_hh  = (const float*)d_in[8];
    const float* fc1_w = (const float*)d_in[9];
    const float* fc1_b = (const float*)d_in[10];
    const float* fc2_w = (const float*)d_in[11];
    const float* fc2_b = (const float*)d_in[12];
    float* out = (float*)d_out;

    bf16 *p_xcat, *p_Wx, *p_hall, *p_fc1;
    float *p_bias, *p_xg, *p_hidden;
    cudaGetSymbolAddress((void**)&p_xcat,   g_xcat);
    cudaGetSymbolAddress((void**)&p_Wx,     g_Wx);
    cudaGetSymbolAddress((void**)&p_bias,   g_bias);
    cudaGetSymbolAddress((void**)&p_xg,     g_xg);
    cudaGetSymbolAddress((void**)&p_hall,   g_hall);
    cudaGetSymbolAddress((void**)&p_fc1,    g_fc1);
    cudaGetSymbolAddress((void**)&p_hidden, g_hidden);

    static bool attr_done = false;
    if (!attr_done) {
        cudaFuncSetAttribute(lstm_persistent,
                             cudaFuncAttributeMaxDynamicSharedMemorySize,
                             REC_SMEM_BYTES);
        attr_done = true;
    }

    // launch 0: pack
    k_pack<<<BT, DPAD>>>(m_text, m_audio, m_video);
    // launch 1: weight prep + state init
    k_prep_all<<<(N_PREP + 255) / 256, 256>>>(W_ih, W_hh, b_ih, b_hh, fc1_w);
    // launch 2: x_gates = xcat @ Wx^T + bias  [65536 x 4096]
    {
        dim3 grid(G4 / 128, BT / 128);
        bf16_gemm<0><<<grid, 256>>>(p_xcat, p_Wx, p_xg, BT, G4, DPAD, p_bias);
    }
    // launch 3: persistent LSTM recurrence
    lstm_persistent<<<NCTA_REC, 256, REC_SMEM_BYTES>>>();
    // launch 4: fc1 + ReLU  [65536 x 512]
    {
        dim3 grid(CD / 128, BT / 128);
        bf16_gemm<1><<<grid, 256>>>(p_hall, p_fc1, p_hidden, BT, CD, HD, fc1_b);
    }
    // launch 5: fc2 + log_softmax
    head_kernel<<<BT / 8, 256>>>(fc2_w, fc2_b, out);
}

// round 11
// speedup vs baseline: 5.2607x; 1.1206x over previous
#include <cuda_runtime.h>
#include <cuda_bf16.h>
#include <math.h>

// Problem constants
#define BATCH 128
#define TT    512
#define BT    65536
#define DIN   409
#define DPAD  416
#define HD    1024
#define G4    4096
#define CD    512
#define OD    7
#define NCTA_REC 128

typedef __nv_bfloat16 bf16;

// -------------------- scratch (static __device__, no allocs) -----------------
__device__ bf16  g_xcat[(size_t)BT * DPAD];   // concat input bf16 [m][k]
__device__ bf16  g_Wx[(size_t)G4 * DPAD];     // W_ih gate-interleaved [n][k]
__device__ float g_bias[G4];                  // b_ih + b_hh gate-interleaved
__device__ bf16  g_Wh[(size_t)G4 * HD];       // W_hh gate-interleaved [n][k]
__device__ float g_xg[(size_t)BT * G4];       // x_gates fp32 [b][t][4H]
__device__ bf16  g_h[2][BATCH * HD];          // double-buffered h
__device__ bf16  g_hall[(size_t)BT * HD];     // all h outputs [b*T+t][h]
__device__ bf16  g_fc1[(size_t)CD * HD];      // fc1_w bf16 [n][k]
__device__ float g_hidden[(size_t)BT * CD];   // relu(fc1) fp32

__device__ unsigned g_bar_count;
__device__ volatile unsigned g_bar_gen;

__device__ __forceinline__ float sigf(float x) {
    return 1.0f / (1.0f + __expf(-x));
}
__device__ __forceinline__ float tanhfast(float x) {
    x = fminf(fmaxf(x, -15.0f), 15.0f);
    float e = __expf(2.0f * x);
    return (e - 1.0f) * __frcp_rn(e + 1.0f);
}
__device__ __forceinline__ void mma_bf16(float c[4],
                                         unsigned a0, unsigned a1, unsigned a2, unsigned a3,
                                         unsigned b0, unsigned b1) {
    asm volatile(
        "mma.sync.aligned.m16n8k16.row.col.f32.bf16.bf16.f32 "
        "{%0,%1,%2,%3},{%4,%5,%6,%7},{%8,%9},{%0,%1,%2,%3};"
        : "+f"(c[0]), "+f"(c[1]), "+f"(c[2]), "+f"(c[3])
        : "r"(a0), "r"(a1), "r"(a2), "r"(a3), "r"(b0), "r"(b1));
}
__device__ __forceinline__ void ldsm_x4(unsigned& r0, unsigned& r1,
                                        unsigned& r2, unsigned& r3, unsigned addr) {
    asm volatile("ldmatrix.sync.aligned.m8n8.x4.shared.b16 {%0,%1,%2,%3}, [%4];"
                 : "=r"(r0), "=r"(r1), "=r"(r2), "=r"(r3) : "r"(addr));
}
__device__ __forceinline__ void cp16(unsigned smem_addr, const void* gptr) {
    asm volatile("cp.async.cg.shared.global [%0], [%1], 16;"
                 :: "r"(smem_addr), "l"(gptr));
}
__device__ __forceinline__ void cp_commit() {
    asm volatile("cp.async.commit_group;");
}
template <int N> __device__ __forceinline__ void cp_waitg() {
    asm volatile("cp.async.wait_group %0;" :: "n"(N));
}

// -------------------- pack: concat -> bf16, pad to 416 -----------------------
__global__ void k_pack(const float* __restrict__ mt,
                       const float* __restrict__ ma,
                       const float* __restrict__ mv) {
    size_t row = blockIdx.x;
    int col = threadIdx.x;          // blockDim = 416
    float v = 0.0f;
    if (col < 300)      v = mt[row * 300 + col];
    else if (col < 374) v = ma[row * 74 + (col - 300)];
    else if (col < 409) v = mv[row * 35 + (col - 374)];
    g_xcat[row * DPAD + col] = __float2bfloat16_rn(v);
}

// -------------------- fused prep ---------------------------------------------
#define N_WX   (G4 * DPAD)
#define N_WH   (G4 * HD)
#define N_FC1  (CD * HD)
#define N_ZERO (BATCH * HD)
#define N_PREP (N_WX + N_WH + G4 + N_FC1 + N_ZERO)

__global__ void k_prep_all(const float* __restrict__ W_ih,
                           const float* __restrict__ W_hh,
                           const float* __restrict__ b_ih,
                           const float* __restrict__ b_hh,
                           const float* __restrict__ fc1_w) {
    long idx = (long)blockIdx.x * 256 + threadIdx.x;
    if (idx == 0) { g_bar_count = 0; g_bar_gen = 0; }
    if (idx < N_WX) {
        int n = (int)(idx / DPAD), k = (int)(idx % DPAD);
        int j = n >> 2, g = n & 3;
        g_Wx[idx] = (k < DIN) ? __float2bfloat16_rn(W_ih[(size_t)(g * HD + j) * DIN + k])
                              : __float2bfloat16_rn(0.0f);
        return;
    }
    idx -= N_WX;
    if (idx < N_WH) {
        int n = (int)(idx / HD), k = (int)(idx % HD);
        int j = n >> 2, g = n & 3;
        g_Wh[idx] = __float2bfloat16_rn(W_hh[(size_t)(g * HD + j) * HD + k]);
        return;
    }
    idx -= N_WH;
    if (idx < G4) {
        int j = (int)(idx >> 2), g = (int)(idx & 3);
        g_bias[idx] = b_ih[g * HD + j] + b_hh[g * HD + j];
        return;
    }
    idx -= G4;
    if (idx < N_FC1) {
        g_fc1[idx] = __float2bfloat16_rn(fc1_w[idx]);
        return;
    }
    idx -= N_FC1;
    if (idx < N_ZERO) g_h[0][idx] = __float2bfloat16_rn(0.0f);
}

// -------------------- bf16 NT GEMM, 3-stage cp.async + ldmatrix --------------
// C[M][N] = A[M][K]*B[N][K]^T + bias (, ReLU). BM=BN=128, BK=32, 256 thr.
#define GS_TILE 5120                 // 128*40 bf16 per stage per operand
#define GEMM_SMEM_BYTES (3 * 2 * GS_TILE * 2)

template <int RELU>
__global__ __launch_bounds__(256) void bf16_gemm(
    const bf16* __restrict__ A, const bf16* __restrict__ B,
    float* __restrict__ C, int M, int N, int K,
    const float* __restrict__ bias) {
    extern __shared__ bf16 sm[];
    bf16* As = sm;                    // [3][128][40]
    bf16* Bs = sm + 3 * GS_TILE;      // [3][128][40]
    const int tid = threadIdx.x;
    const int bm = blockIdx.y, bn = blockIdx.x;
    const int lane = tid & 31, wid = tid >> 5;
    const int gid = lane >> 2, tig = lane & 3;
    const int lrow = lane & 7, lmat = lane >> 3;
    const int mbase = (wid >> 2) * 64, nbase = (wid & 3) * 32;

    const unsigned as_u32 = (unsigned)__cvta_generic_to_shared(As);
    const unsigned bs_u32 = (unsigned)__cvta_generic_to_shared(Bs);

    // loader coords: each thread loads 32 contiguous bytes per operand:
    // row = tid>>1 (0..127), kbase = (tid&1)*16 (0 or 16), chunks at +0,+8.
    const int gr = tid >> 1;
    const int gk = (tid & 1) * 16;
    const bf16* Ab = A + (size_t)bm * 128 * K;
    const bf16* Bb = B + (size_t)bn * 128 * K;

    // ldmatrix offsets (elements)
    int a_eoff[4];
#pragma unroll
    for (int mi = 0; mi < 4; mi++)
        a_eoff[mi] = (mbase + mi * 16 + (lmat & 1) * 8 + lrow) * 40 + (lmat >> 1) * 8;
    int b_eoff[2];
#pragma unroll
    for (int nh = 0; nh < 2; nh++)
        b_eoff[nh] = (nbase + nh * 16 + (lmat >> 1) * 8 + lrow) * 40 + (lmat & 1) * 8;

    float acc[4][4][4];
#pragma unroll
    for (int i = 0; i < 4; i++)
#pragma unroll
        for (int j = 0; j < 4; j++)
#pragma unroll
            for (int q = 0; q < 4; q++) acc[i][j][q] = 0.0f;

#define G_ISSUE(s, k0)                                                          \
    do {                                                                        \
        cp16(as_u32 + (unsigned)((s) * GS_TILE + gr * 40 + gk) * 2,             \
             Ab + (size_t)gr * K + (k0) + gk);                                  \
        cp16(as_u32 + (unsigned)((s) * GS_TILE + gr * 40 + gk + 8) * 2,         \
             Ab + (size_t)gr * K + (k0) + gk + 8);                              \
        cp16(bs_u32 + (unsigned)((s) * GS_TILE + gr * 40 + gk) * 2,             \
             Bb + (size_t)gr * K + (k0) + gk);                                  \
        cp16(bs_u32 + (unsigned)((s) * GS_TILE + gr * 40 + gk + 8) * 2,         \
             Bb + (size_t)gr * K + (k0) + gk + 8);                              \
        cp_commit();                                                            \
    } while (0)

    const int niter = K >> 5;         // K/32
    G_ISSUE(0, 0);
    G_ISSUE(1, 32);

    for (int it = 0; it < niter; it++) {
        if (it == niter - 1) cp_waitg<0>(); else cp_waitg<1>();
        __syncthreads();
        if (it + 2 < niter) G_ISSUE((it + 2) % 3, (it + 2) * 32);

        const unsigned ab = as_u32 + (unsigned)((it % 3) * GS_TILE) * 2;
        const unsigned bb = bs_u32 + (unsigned)((it % 3) * GS_TILE) * 2;
#pragma unroll
        for (int kk = 0; kk < 32; kk += 16) {
            unsigned a[4][4], bq[2][4];
#pragma unroll
            for (int mi = 0; mi < 4; mi++)
                ldsm_x4(a[mi][0], a[mi][1], a[mi][2], a[mi][3],
                        ab + (unsigned)(a_eoff[mi] + kk) * 2);
#pragma unroll
            for (int nh = 0; nh < 2; nh++)
                ldsm_x4(bq[nh][0], bq[nh][1], bq[nh][2], bq[nh][3],
                        bb + (unsigned)(b_eoff[nh] + kk) * 2);
#pragma unroll
            for (int mi = 0; mi < 4; mi++) {
                mma_bf16(acc[mi][0], a[mi][0], a[mi][1], a[mi][2], a[mi][3],
                         bq[0][0], bq[0][1]);
                mma_bf16(acc[mi][1], a[mi][0], a[mi][1], a[mi][2], a[mi][3],
                         bq[0][2], bq[0][3]);
                mma_bf16(acc[mi][2], a[mi][0], a[mi][1], a[mi][2], a[mi][3],
                         bq[1][0], bq[1][1]);
                mma_bf16(acc[mi][3], a[mi][0], a[mi][1], a[mi][2], a[mi][3],
                         bq[1][2], bq[1][3]);
            }
        }
    }
#undef G_ISSUE

#pragma unroll
    for (int mi = 0; mi < 4; mi++) {
        int r = mbase + mi * 16 + gid;
#pragma unroll
        for (int ni = 0; ni < 4; ni++) {
            int cc = nbase + ni * 8 + tig * 2;
            float bb0 = bias[bn * 128 + cc];
            float bb1 = bias[bn * 128 + cc + 1];
            float v0 = acc[mi][ni][0] + bb0, v1 = acc[mi][ni][1] + bb1;
            float v2 = acc[mi][ni][2] + bb0, v3 = acc[mi][ni][3] + bb1;
            if (RELU) {
                v0 = fmaxf(v0, 0.0f); v1 = fmaxf(v1, 0.0f);
                v2 = fmaxf(v2, 0.0f); v3 = fmaxf(v3, 0.0f);
            }
            *(float2*)(C + ((size_t)bm * 128 + r) * N + bn * 128 + cc)     = make_float2(v0, v1);
            *(float2*)(C + ((size_t)bm * 128 + r + 8) * N + bn * 128 + cc) = make_float2(v2, v3);
        }
    }
}

// -------------------- persistent fused LSTM recurrence -----------------------
// 128 CTAs x 256 threads; CTA b owns gate cols [32b,32b+32) = units [8b,8b+8).
// 4-buffer h pipeline (prefetch distance 3) + ldmatrix + fused epilogue.
#define WS_STRIDE 1032
#define HS_STRIDE 136
#define KCHUNK 128
#define NCHUNK (HD / KCHUNK)                 // 8
#define NBUF 4
#define WS_ELE (32 * WS_STRIDE)              // 33024
#define HS_ELE (BATCH * HS_STRIDE)           // 17408 per buffer
#define REC_SMEM_BYTES ((WS_ELE + NBUF * HS_ELE + BATCH * 8) * 2)

__global__ __launch_bounds__(256, 1) void lstm_persistent() {
    extern __shared__ bf16 smem[];
    bf16* Ws = smem;                         // [32][1032]
    bf16* Hs = smem + WS_ELE;                // [4][128][136]
    bf16* h_stage = Hs + NBUF * HS_ELE;      // [128][8]

    const int tid = threadIdx.x;
    const int lane = tid & 31, wid = tid >> 5;
    const int gid = lane >> 2, tig = lane & 3;
    const int lrow = lane & 7, lmat = lane >> 3;
    const int n0 = blockIdx.x * 32;
    const int ubase = blockIdx.x * 8;
    const int mbase = (wid >> 1) * 32;       // 4 warps over m=128
    const int nbase = (wid & 1) * 16;        // 2 warps over n=32

    const unsigned ws_u32 = (unsigned)__cvta_generic_to_shared(Ws);
    const unsigned hs_u32 = (unsigned)__cvta_generic_to_shared(Hs);

    // load Wh slice once: 32 cols x 1024 k
    for (int i = tid; i < 32 * 128; i += 256) {
        int c = i >> 7, kv = (i & 127) * 8;
        *(uint4*)&Ws[c * WS_STRIDE + kv] =
            *(const uint4*)&g_Wh[(size_t)(n0 + c) * HD + kv];
    }

    int a_eoff[2];
#pragma unroll
    for (int mi = 0; mi < 2; mi++)
        a_eoff[mi] = (mbase + mi * 16 + (lmat & 1) * 8 + lrow) * HS_STRIDE + (lmat >> 1) * 8;
    const int b_eoff = (nbase + (lmat >> 1) * 8 + lrow) * WS_STRIDE + (lmat & 1) * 8;

    // cp.async coords: 2048 16B-chunks per 32KB h tile; 8 per thread
    const int crow = tid >> 4, ck16 = (tid & 15) * 8;   // rows crow + r*16

    float c_reg[4];
#pragma unroll
    for (int i = 0; i < 4; i++) c_reg[i] = 0.0f;

    int ep_row[2][2], ep_lu[2][2];
#pragma unroll
    for (int mi = 0; mi < 2; mi++)
#pragma unroll
        for (int ni = 0; ni < 2; ni++) {
            ep_row[mi][ni] = mbase + mi * 16 + gid + ((tig & 1) ? 8 : 0);
            ep_lu[mi][ni] = (nbase >> 2) + ni * 2 + (tig >> 1);
        }

    __syncthreads();   // Ws ready

#define H_ISSUE(buf, k0)                                                        \
    do {                                                                        \
        const unsigned d = hs_u32 + (unsigned)((buf) * HS_ELE) * 2;             \
        _Pragma("unroll")                                                       \
        for (int r = 0; r < 8; r++) {                                           \
            int row = crow + r * 16;                                            \
            cp16(d + (unsigned)(row * HS_STRIDE + ck16) * 2,                    \
                 hprev + (size_t)row * HD + (k0) + ck16);                       \
        }                                                                       \
        cp_commit();                                                            \
    } while (0)

    for (int t = 0; t < TT; t++) {
        const bf16* __restrict__ hprev = g_h[t & 1];
        bf16* __restrict__ hnext = g_h[(t + 1) & 1];

        float acc[2][2][4];
#pragma unroll
        for (int i = 0; i < 2; i++)
#pragma unroll
            for (int j = 0; j < 2; j++)
#pragma unroll
                for (int q = 0; q < 4; q++) acc[i][j][q] = 0.0f;

        // prefetch x_gates (DRAM) into registers
        float4 xg[2][2];
#pragma unroll
        for (int mi = 0; mi < 2; mi++)
#pragma unroll
            for (int ni = 0; ni < 2; ni++)
                xg[mi][ni] = *(const float4*)(g_xg +
                    ((size_t)ep_row[mi][ni] * TT + t) * G4 + n0 + ep_lu[mi][ni] * 4);

        // prologue: issue chunks 0..2
        H_ISSUE(0, 0);
        H_ISSUE(1, KCHUNK);
        H_ISSUE(2, 2 * KCHUNK);

#pragma unroll
        for (int ch = 0; ch < NCHUNK; ch++) {
            if (ch < NCHUNK - 2)       cp_waitg<2>();
            else if (ch == NCHUNK - 2) cp_waitg<1>();
            else                       cp_waitg<0>();
            __syncthreads();
            if (ch + 3 < NCHUNK) H_ISSUE((ch + 3) & 3, (ch + 3) * KCHUNK);

            const unsigned hb = hs_u32 + (unsigned)((ch & 3) * HS_ELE) * 2;
            const int k0 = ch * KCHUNK;
#pragma unroll
            for (int kk = 0; kk < KCHUNK; kk += 16) {
                unsigned a[2][4], b[4];
                ldsm_x4(a[0][0], a[0][1], a[0][2], a[0][3],
                        hb + (unsigned)(a_eoff[0] + kk) * 2);
                ldsm_x4(a[1][0], a[1][1], a[1][2], a[1][3],
                        hb + (unsigned)(a_eoff[1] + kk) * 2);
                ldsm_x4(b[0], b[1], b[2], b[3],
                        ws_u32 + (unsigned)(b_eoff + k0 + kk) * 2);
#pragma unroll
                for (int mi = 0; mi < 2; mi++) {
                    mma_bf16(acc[mi][0], a[mi][0], a[mi][1], a[mi][2], a[mi][3],
                             b[0], b[1]);
                    mma_bf16(acc[mi][1], a[mi][0], a[mi][1], a[mi][2], a[mi][3],
                             b[2], b[3]);
                }
            }
        }

        // ---- fused LSTM epilogue ----
#pragma unroll
        for (int mi = 0; mi < 2; mi++) {
#pragma unroll
            for (int ni = 0; ni < 2; ni++) {
                float* A = acc[mi][ni];
                float p0 = __shfl_xor_sync(0xFFFFFFFFu, A[0], 1);
                float p1 = __shfl_xor_sync(0xFFFFFFFFu, A[1], 1);
                float p2 = __shfl_xor_sync(0xFFFFFFFFu, A[2], 1);
                float p3 = __shfl_xor_sync(0xFFFFFFFFu, A[3], 1);
                float gi, gf, gg, go;
                if ((tig & 1) == 0) { gi = A[0]; gf = A[1]; gg = p0; go = p1; }
                else                { gi = p2;  gf = p3;  gg = A[2]; go = A[3]; }
                float4 x = xg[mi][ni];
                gi += x.x; gf += x.y; gg += x.z; go += x.w;
                float iv = sigf(gi);
                float fv = sigf(gf);
                float gv = tanhfast(gg);
                float ov = sigf(go);
                float cn = fmaf(fv, c_reg[mi * 2 + ni], iv * gv);
                c_reg[mi * 2 + ni] = cn;
                float hn = ov * tanhfast(cn);
                h_stage[ep_row[mi][ni] * 8 + ep_lu[mi][ni]] = __float2bfloat16_rn(hn);
            }
        }
        __syncthreads();

        // coalesced h writes
        if (tid < 128) {
            uint4 v = *(uint4*)&h_stage[tid * 8];
            *(uint4*)(hnext + (size_t)tid * HD + ubase) = v;
            *(uint4*)(g_hall + ((size_t)tid * TT + t) * HD + ubase) = v;
        }

        // ---- software grid barrier ----
        __threadfence();
        __syncthreads();
        if (tid == 0) {
            unsigned prev = atomicAdd(&g_bar_count, 1u);
            if (prev == NCTA_REC - 1) {
                g_bar_count = 0;
                __threadfence();
                g_bar_gen = (unsigned)(t + 1);
            } else {
                while (g_bar_gen < (unsigned)(t + 1)) __nanosleep(32);
            }
            __threadfence();
        }
        __syncthreads();
    }
#undef H_ISSUE
}

// -------------------- head: fc2 (N=7) + log_softmax --------------------------
__global__ __launch_bounds__(256) void head_kernel(const float* __restrict__ fc2_w,
                                                   const float* __restrict__ fc2_b,
                                                   float* __restrict__ out) {
    __shared__ float ws[OD][CD];
    const int tid = threadIdx.x;
    for (int i = tid; i < OD * CD; i += 256) ws[i / CD][i % CD] = fc2_w[i];
    __syncthreads();

    const int warp = tid >> 5, lane = tid & 31;
    size_t row = (size_t)blockIdx.x * 8 + warp;
    const float* h = g_hidden + row * CD;

    float p[OD];
#pragma unroll
    for (int o = 0; o < OD; o++) p[o] = 0.0f;

    for (int k = lane; k < CD; k += 32) {
        float hv = h[k];
#pragma unroll
        for (int o = 0; o < OD; o++) p[o] = fmaf(hv, ws[o][k], p[o]);
    }
#pragma unroll
    for (int o = 0; o < OD; o++)
#pragma unroll
        for (int s = 16; s > 0; s >>= 1)
            p[o] += __shfl_xor_sync(0xFFFFFFFFu, p[o], s);

    float z[OD], m = -1e30f;
#pragma unroll
    for (int o = 0; o < OD; o++) { z[o] = p[o] + fc2_b[o]; m = fmaxf(m, z[o]); }
    float s = 0.0f;
#pragma unroll
    for (int o = 0; o < OD; o++) s += expf(z[o] - m);
    float lse = m + logf(s);
    if (lane < OD) out[row * OD + lane] = z[lane] - lse;
}

// -------------------- launch ------------------------------------------------
extern "C" void kernel_launch(void* const* d_in, const int* in_sizes, int n_in,
                              void* d_out, int out_size) {
    const float* m_text  = (const float*)d_in[0];
    const float* m_audio = (const float*)d_in[1];
    const float* m_video = (const float*)d_in[2];
    const float* W_ih  = (const float*)d_in[5];
    const float* W_hh  = (const float*)d_in[6];
    const float* b_ih  = (const float*)d_in[7];
    const float* b_hh  = (const float*)d_in[8];
    const float* fc1_w = (const float*)d_in[9];
    const float* fc1_b = (const float*)d_in[10];
    const float* fc2_w = (const float*)d_in[11];
    const float* fc2_b = (const float*)d_in[12];
    float* out = (float*)d_out;

    bf16 *p_xcat, *p_Wx, *p_hall, *p_fc1;
    float *p_bias, *p_xg, *p_hidden;
    cudaGetSymbolAddress((void**)&p_xcat,   g_xcat);
    cudaGetSymbolAddress((void**)&p_Wx,     g_Wx);
    cudaGetSymbolAddress((void**)&p_bias,   g_bias);
    cudaGetSymbolAddress((void**)&p_xg,     g_xg);
    cudaGetSymbolAddress((void**)&p_hall,   g_hall);
    cudaGetSymbolAddress((void**)&p_fc1,    g_fc1);
    cudaGetSymbolAddress((void**)&p_hidden, g_hidden);

    static bool attr_done = false;
    if (!attr_done) {
        cudaFuncSetAttribute(lstm_persistent,
                             cudaFuncAttributeMaxDynamicSharedMemorySize,
                             REC_SMEM_BYTES);
        cudaFuncSetAttribute(bf16_gemm<0>,
                             cudaFuncAttributeMaxDynamicSharedMemorySize,
                             GEMM_SMEM_BYTES);
        cudaFuncSetAttribute(bf16_gemm<1>,
                             cudaFuncAttributeMaxDynamicSharedMemorySize,
                             GEMM_SMEM_BYTES);
        attr_done = true;
    }

    // launch 0: pack
    k_pack<<<BT, DPAD>>>(m_text, m_audio, m_video);
    // launch 1: weight prep + state init
    k_prep_all<<<(N_PREP + 255) / 256, 256>>>(W_ih, W_hh, b_ih, b_hh, fc1_w);
    // launch 2: x_gates = xcat @ Wx^T + bias  [65536 x 4096]
    {
        dim3 grid(G4 / 128, BT / 128);
        bf16_gemm<0><<<grid, 256, GEMM_SMEM_BYTES>>>(p_xcat, p_Wx, p_xg, BT, G4, DPAD, p_bias);
    }
    // launch 3: persistent LSTM recurrence
    lstm_persistent<<<NCTA_REC, 256, REC_SMEM_BYTES>>>();
    // launch 4: fc1 + ReLU  [65536 x 512]
    {
        dim3 grid(CD / 128, BT / 128);
        bf16_gemm<1><<<grid, 256, GEMM_SMEM_BYTES>>>(p_hall, p_fc1, p_hidden, BT, CD, HD, fc1_b);
    }
    // launch 5: fc2 + log_softmax
    head_kernel<<<BT / 8, 256>>>(fc2_w, fc2_b, out);
}